// round 4
// baseline (speedup 1.0000x reference)
#include <cuda_runtime.h>
#include <math.h>

// Problem constants
#define B_  2
#define E_  1024
#define DM_ 512
#define H_  8
#define DK_ 64
#define DV_ 64
#define MAXN_ 5
#define NEGV (-1e9f)

// TF32 quantization (harmless vs exact-fp32 reference, matches a tf32 GPU ref)
__device__ __forceinline__ float tf32q(float x) {
    unsigned u;
    asm("cvt.rna.tf32.f32 %0, %1;" : "=r"(u) : "f"(x));
    return __uint_as_float(u);
}
__device__ __forceinline__ float4 tf32q4(float4 v) {
    v.x = tf32q(v.x); v.y = tf32q(v.y); v.z = tf32q(v.z); v.w = tf32q(v.w);
    return v;
}

// ---------------- scratch (device globals; no allocation allowed) ----------
__device__ float g_s [B_*E_*DM_];       // x transposed: [b,e,d]
__device__ float g_qn[B_*E_*DM_];       // layernormed s
__device__ float g_q [B_*H_*E_*DK_];    // scaled by 1/8
__device__ float g_k [B_*H_*E_*DK_];
__device__ float g_v [B_*H_*E_*DV_];
__device__ float g_qr[B_*H_*E_*6];      // qs . base_rpr[c]
__device__ float g_o [B_*E_*H_*DV_];    // attn @ v, layout [b,e,h*64+d]
__device__ float g_pcs [16*B_*E_];      // partial column sums of attn*mask
__device__ float g_pcnt[16*B_*E_];      // partial mask counts

// ---------------- 1. transpose x[b,d,e] -> s[b,e,d] ------------------------
__global__ void k_transpose(const float* __restrict__ x) {
    __shared__ float tile[32][33];
    int b = blockIdx.z;
    int e0 = blockIdx.x * 32;
    int d0 = blockIdx.y * 32;
    int tx = threadIdx.x, ty = threadIdx.y;
#pragma unroll
    for (int r = 0; r < 4; r++) {
        int d = d0 + ty + r * 8;
        tile[ty + r * 8][tx] = x[(size_t)b * DM_ * E_ + (size_t)d * E_ + e0 + tx];
    }
    __syncthreads();
#pragma unroll
    for (int r = 0; r < 4; r++) {
        int e = e0 + ty + r * 8;
        g_s[(size_t)b * E_ * DM_ + (size_t)e * DM_ + d0 + tx] = tile[tx][ty + r * 8];
    }
}

// ---------------- 2. LayerNorm rows of s -> qn ------------------------------
__global__ void k_layernorm(const float* __restrict__ ln_g, const float* __restrict__ ln_b) {
    int row = blockIdx.x;                       // b*E + e
    const float* src = g_s + (size_t)row * DM_;
    int tid = threadIdx.x;                      // 256 threads, 2 floats each
    float2 v = ((const float2*)src)[tid];
    float s1 = v.x + v.y;
    float s2 = v.x * v.x + v.y * v.y;
#pragma unroll
    for (int o = 16; o; o >>= 1) {
        s1 += __shfl_xor_sync(0xffffffff, s1, o);
        s2 += __shfl_xor_sync(0xffffffff, s2, o);
    }
    __shared__ float sh[16];
    __shared__ float s_mu, s_rstd;
    int w = tid >> 5, l = tid & 31;
    if (l == 0) { sh[w] = s1; sh[8 + w] = s2; }
    __syncthreads();
    if (tid == 0) {
        float a = 0.f, c = 0.f;
#pragma unroll
        for (int i = 0; i < 8; i++) { a += sh[i]; c += sh[8 + i]; }
        float mu  = a / (float)DM_;
        float var = c / (float)DM_ - mu * mu;
        s_mu = mu;
        s_rstd = 1.f / sqrtf(var + 1e-6f);
    }
    __syncthreads();
    float mu = s_mu, rstd = s_rstd;
    float2 gg = ((const float2*)ln_g)[tid];
    float2 bb = ((const float2*)ln_b)[tid];
    float2 o;
    o.x = (v.x - mu) * rstd * gg.x + bb.x;
    o.y = (v.y - mu) * rstd * gg.y + bb.y;
    ((float2*)(g_qn + (size_t)row * DM_))[tid] = o;
}

// ---------------- shared GEMM inner macro ----------------------------------
#define FMA16(a, bv)                                                         \
    acc[0][0] += a.x * bv.x; acc[0][1] += a.x * bv.y;                        \
    acc[0][2] += a.x * bv.z; acc[0][3] += a.x * bv.w;                        \
    acc[1][0] += a.y * bv.x; acc[1][1] += a.y * bv.y;                        \
    acc[1][2] += a.y * bv.z; acc[1][3] += a.y * bv.w;                        \
    acc[2][0] += a.z * bv.x; acc[2][1] += a.z * bv.y;                        \
    acc[2][2] += a.z * bv.z; acc[2][3] += a.z * bv.w;                        \
    acc[3][0] += a.w * bv.x; acc[3][1] += a.w * bv.y;                        \
    acc[3][2] += a.w * bv.z; acc[3][3] += a.w * bv.w;

// ---------------- 3. QKV GEMM: out[b,h,e,d] = A[b] @ W (per-head column tile)
// grid (E/64, H, B), 256 threads
__global__ __launch_bounds__(256) void k_gemm_qkv(
    const float* __restrict__ A, const float* __restrict__ W,
    float* __restrict__ out, float scale)
{
    __shared__ float As[16][68];
    __shared__ float Bs[16][64];
    int b = blockIdx.z, h = blockIdx.y;
    int m0 = blockIdx.x * 64;
    int tid = threadIdx.x;
    int tx = tid & 15, ty = tid >> 4;
    const float* Ab = A + (size_t)b * E_ * DM_ + (size_t)m0 * DM_;
    const float* Wb = W + h * 64;
    float acc[4][4] = {};
    int arow = tid >> 2, acol = (tid & 3) * 4;
    int brow = tid >> 4, bcol = (tid & 15) * 4;
    for (int k0 = 0; k0 < DM_; k0 += 16) {
        float4 av = tf32q4(*(const float4*)(Ab + (size_t)arow * DM_ + k0 + acol));
        As[acol + 0][arow] = av.x; As[acol + 1][arow] = av.y;
        As[acol + 2][arow] = av.z; As[acol + 3][arow] = av.w;
        float4 bv4 = tf32q4(*(const float4*)(Wb + (size_t)(k0 + brow) * (H_ * DK_) + bcol));
        *(float4*)&Bs[brow][bcol] = bv4;
        __syncthreads();
#pragma unroll
        for (int k = 0; k < 16; k++) {
            float4 a  = *(const float4*)&As[k][ty * 4];
            float4 bv = *(const float4*)&Bs[k][tx * 4];
            FMA16(a, bv)
        }
        __syncthreads();
    }
    float* ob = out + (((size_t)b * H_ + h) * E_ + m0) * DK_;
#pragma unroll
    for (int ii = 0; ii < 4; ii++) {
        float4 o;
        o.x = acc[ii][0] * scale; o.y = acc[ii][1] * scale;
        o.z = acc[ii][2] * scale; o.w = acc[ii][3] * scale;
        *(float4*)(ob + (size_t)(ty * 4 + ii) * DK_ + tx * 4) = o;
    }
}

// ---------------- 4. qr[b,h,i,c] = qs . base_rpr[c] -------------------------
__global__ void k_qr(const float* __restrict__ base_rpr) {
    __shared__ float rpr[6 * 64];
    int tid = threadIdx.x;
    // FIX: 384 entries, 256 threads -> strided fill (was `if (tid < 384)`,
    // leaving rpr[256..383] (c=4,5) uninitialized)
    for (int t = tid; t < 384; t += 256) rpr[t] = tf32q(base_rpr[t]);
    __syncthreads();
    int idx = blockIdx.x * 256 + tid;          // 0 .. 98303
    int row = idx / 6, c = idx % 6;
    const float* q = g_q + (size_t)row * DK_;
    float s = 0.f;
#pragma unroll 8
    for (int d = 0; d < DK_; d++) s += tf32q(q[d]) * rpr[c * 64 + d];
    g_qr[(size_t)row * 6 + c] = s;
}

// ---------------- 5. logits: qs @ k^T + qr[dist] (masked) -> attn buffer ----
// grid (E/64, H, B), 256 threads
__global__ __launch_bounds__(256) void k_logits(
    const int* __restrict__ dist, float* __restrict__ attn)
{
    __shared__ float Qs[64][68];
    __shared__ float Ks[64][68];
    __shared__ float qrs[64][8];
    int b = blockIdx.z, h = blockIdx.y;
    int i0 = blockIdx.x * 64;
    int tid = threadIdx.x;
    int tx = tid & 15, ty = tid >> 4;
    int lrow = tid >> 4, lcol = (tid & 15) * 4;

    size_t qbase = (((size_t)b * H_ + h) * E_ + i0) * DK_;
#pragma unroll
    for (int r = 0; r < 4; r++) {
        int i = lrow + r * 16;
        float4 v = tf32q4(*(const float4*)(g_q + qbase + (size_t)i * DK_ + lcol));
        Qs[lcol + 0][i] = v.x; Qs[lcol + 1][i] = v.y;
        Qs[lcol + 2][i] = v.z; Qs[lcol + 3][i] = v.w;
    }
    // FIX: 384 entries, 256 threads -> strided fill (was `if (tid < 384)`,
    // leaving qrs rows 43..63 uninitialized)
    for (int t = tid; t < 384; t += 256) {
        int i = t / 6, c = t % 6;
        qrs[i][c] = g_qr[(((size_t)b * H_ + h) * E_ + i0 + i) * 6 + c];
    }

    float* arow_out = attn + (((size_t)b * H_ + h) * E_ + i0) * E_;
    const int* drow = dist + (size_t)b * E_ * E_;

    for (int jt = 0; jt < 16; jt++) {
        int j0 = jt * 64;
        size_t kbase = (((size_t)b * H_ + h) * E_ + j0) * DK_;
#pragma unroll
        for (int r = 0; r < 4; r++) {
            int j = lrow + r * 16;
            float4 v = tf32q4(*(const float4*)(g_k + kbase + (size_t)j * DK_ + lcol));
            Ks[lcol + 0][j] = v.x; Ks[lcol + 1][j] = v.y;
            Ks[lcol + 2][j] = v.z; Ks[lcol + 3][j] = v.w;
        }
        __syncthreads();
        float acc[4][4] = {};
#pragma unroll 16
        for (int d = 0; d < 64; d++) {
            float4 a  = *(const float4*)&Qs[d][ty * 4];
            float4 bv = *(const float4*)&Ks[d][tx * 4];
            FMA16(a, bv)
        }
#pragma unroll
        for (int ii = 0; ii < 4; ii++) {
            int i = ty * 4 + ii;
            int4 dd = *(const int4*)(drow + (size_t)(i0 + i) * E_ + j0 + tx * 4);
            float4 o;
            o.x = (dd.x <= MAXN_) ? acc[ii][0] + qrs[i][dd.x] : NEGV;
            o.y = (dd.y <= MAXN_) ? acc[ii][1] + qrs[i][dd.y] : NEGV;
            o.z = (dd.z <= MAXN_) ? acc[ii][2] + qrs[i][dd.z] : NEGV;
            o.w = (dd.w <= MAXN_) ? acc[ii][3] + qrs[i][dd.w] : NEGV;
            *(float4*)(arow_out + (size_t)i * E_ + j0 + tx * 4) = o;
        }
        __syncthreads();
    }
}

// ---------------- 6. row softmax (in place) ---------------------------------
__global__ void k_softmax(float* __restrict__ attn) {
    size_t base = (size_t)blockIdx.x * E_;
    int tid = threadIdx.x;                      // 256, 4 floats each
    float4 v = ((float4*)(attn + base))[tid];
    float m = fmaxf(fmaxf(v.x, v.y), fmaxf(v.z, v.w));
#pragma unroll
    for (int o = 16; o; o >>= 1) m = fmaxf(m, __shfl_xor_sync(0xffffffff, m, o));
    __shared__ float sh[8];
    __shared__ float s_m, s_inv;
    int w = tid >> 5, l = tid & 31;
    if (l == 0) sh[w] = m;
    __syncthreads();
    if (tid == 0) {
        float mm = sh[0];
#pragma unroll
        for (int i = 1; i < 8; i++) mm = fmaxf(mm, sh[i]);
        s_m = mm;
    }
    __syncthreads();
    m = s_m;
    v.x = expf(v.x - m); v.y = expf(v.y - m);
    v.z = expf(v.z - m); v.w = expf(v.w - m);
    float s = v.x + v.y + v.z + v.w;
#pragma unroll
    for (int o = 16; o; o >>= 1) s += __shfl_xor_sync(0xffffffff, s, o);
    if (l == 0) sh[w] = s;
    __syncthreads();
    if (tid == 0) {
        float ss = 0.f;
#pragma unroll
        for (int i = 0; i < 8; i++) ss += sh[i];
        s_inv = 1.f / ss;
    }
    __syncthreads();
    float inv = s_inv;
    v.x *= inv; v.y *= inv; v.z *= inv; v.w *= inv;
    ((float4*)(attn + base))[tid] = v;
}

// ---------------- 7. O = attn @ V  (K-dim = 1024) ---------------------------
// grid (E/64, H, B), 256 threads
__global__ __launch_bounds__(256) void k_ogemm(const float* __restrict__ attn) {
    __shared__ float As[16][68];
    __shared__ float Bs[16][64];
    int b = blockIdx.z, h = blockIdx.y;
    int m0 = blockIdx.x * 64;
    int tid = threadIdx.x;
    int tx = tid & 15, ty = tid >> 4;
    const float* Ab = attn + (((size_t)b * H_ + h) * E_ + m0) * E_;
    const float* Vb = g_v + (((size_t)b * H_ + h) * E_) * DV_;
    float acc[4][4] = {};
    int arow = tid >> 2, acol = (tid & 3) * 4;
    int brow = tid >> 4, bcol = (tid & 15) * 4;
    for (int k0 = 0; k0 < E_; k0 += 16) {
        float4 av = tf32q4(*(const float4*)(Ab + (size_t)arow * E_ + k0 + acol));
        As[acol + 0][arow] = av.x; As[acol + 1][arow] = av.y;
        As[acol + 2][arow] = av.z; As[acol + 3][arow] = av.w;
        float4 bv4 = tf32q4(*(const float4*)(Vb + (size_t)(k0 + brow) * DV_ + bcol));
        *(float4*)&Bs[brow][bcol] = bv4;
        __syncthreads();
#pragma unroll
        for (int k = 0; k < 16; k++) {
            float4 a  = *(const float4*)&As[k][ty * 4];
            float4 bv = *(const float4*)&Bs[k][tx * 4];
            FMA16(a, bv)
        }
        __syncthreads();
    }
#pragma unroll
    for (int ii = 0; ii < 4; ii++) {
        float4 o;
        o.x = acc[ii][0]; o.y = acc[ii][1]; o.z = acc[ii][2]; o.w = acc[ii][3];
        *(float4*)(g_o + ((size_t)b * E_ + m0 + ty * 4 + ii) * (H_ * DV_)
                       + h * DV_ + tx * 4) = o;
    }
}

// ---------------- 8. FC + residual, write transposed x_out ------------------
// grid (E/64, DM/64, B)
__global__ __launch_bounds__(256) void k_fc(
    const float* __restrict__ w_fc, float* __restrict__ xout)
{
    __shared__ float As[16][68];
    __shared__ float Bs[16][64];
    int b = blockIdx.z;
    int m0 = blockIdx.x * 64, n0 = blockIdx.y * 64;
    int tid = threadIdx.x;
    int tx = tid & 15, ty = tid >> 4;
    const float* Ab = g_o + (size_t)b * E_ * (H_ * DV_) + (size_t)m0 * (H_ * DV_);
    const float* Wb = w_fc + n0;
    float acc[4][4] = {};
    int arow = tid >> 2, acol = (tid & 3) * 4;
    int brow = tid >> 4, bcol = (tid & 15) * 4;
    for (int k0 = 0; k0 < H_ * DV_; k0 += 16) {
        float4 av = tf32q4(*(const float4*)(Ab + (size_t)arow * (H_ * DV_) + k0 + acol));
        As[acol + 0][arow] = av.x; As[acol + 1][arow] = av.y;
        As[acol + 2][arow] = av.z; As[acol + 3][arow] = av.w;
        float4 bv4 = tf32q4(*(const float4*)(Wb + (size_t)(k0 + brow) * DM_ + bcol));
        *(float4*)&Bs[brow][bcol] = bv4;
        __syncthreads();
#pragma unroll
        for (int k = 0; k < 16; k++) {
            float4 a  = *(const float4*)&As[k][ty * 4];
            float4 bv = *(const float4*)&Bs[k][tx * 4];
            FMA16(a, bv)
        }
        __syncthreads();
    }
    // out[b,e,n] + residual s[b,e,n]  ->  x_out[b, n, e]
#pragma unroll
    for (int jj = 0; jj < 4; jj++) {
        int n = n0 + tx * 4 + jj;
        float4 o;
        o.x = acc[0][jj] + g_s[((size_t)b * E_ + m0 + ty * 4 + 0) * DM_ + n];
        o.y = acc[1][jj] + g_s[((size_t)b * E_ + m0 + ty * 4 + 1) * DM_ + n];
        o.z = acc[2][jj] + g_s[((size_t)b * E_ + m0 + ty * 4 + 2) * DM_ + n];
        o.w = acc[3][jj] + g_s[((size_t)b * E_ + m0 + ty * 4 + 3) * DM_ + n];
        *(float4*)(xout + (size_t)b * DM_ * E_ + (size_t)n * E_ + m0 + ty * 4) = o;
    }
}

// ---------------- 9. partial column sums for attn_per_edge ------------------
// grid (E/256, B, 16) — z splits the i range
__global__ void k_colsum_partial(const int* __restrict__ dist,
                                 const float* __restrict__ attn)
{
    int j = blockIdx.x * 256 + threadIdx.x;
    int b = blockIdx.y, z = blockIdx.z;
    float cs = 0.f;
    float cn = 0.f;
    for (int i = z * 64; i < z * 64 + 64; i++) {
        int dv = dist[(size_t)b * E_ * E_ + (size_t)i * E_ + j];
        if (dv <= MAXN_) {
            cn += 1.f;
#pragma unroll
            for (int h = 0; h < H_; h++)
                cs += attn[(((size_t)b * H_ + h) * E_ + i) * E_ + j];
        }
    }
    g_pcs [((size_t)z * B_ + b) * E_ + j] = cs;
    g_pcnt[((size_t)z * B_ + b) * E_ + j] = cn;
}

__global__ void k_colsum_final(float* __restrict__ ape) {
    int idx = blockIdx.x * 256 + threadIdx.x;   // 0 .. B*E-1
    int b = idx >> 10, j = idx & (E_ - 1);
    float cs = 0.f, cn = 0.f;
#pragma unroll
    for (int z = 0; z < 16; z++) {
        cs += g_pcs [((size_t)z * B_ + b) * E_ + j];
        cn += g_pcnt[((size_t)z * B_ + b) * E_ + j];
    }
    // reference: mf = mask[:, None] has a SIZE-1 head axis, so the denominator
    // is count_i only — numerator sums all H heads, denominator does NOT.
    ape[idx] = cs / cn;
}

// ---------------- launch ----------------------------------------------------
extern "C" void kernel_launch(void* const* d_in, const int* in_sizes, int n_in,
                              void* d_out, int out_size) {
    const float* x        = (const float*)d_in[0];
    const int*   dist     = (const int*)  d_in[1];
    const float* base_rpr = (const float*)d_in[2];
    const float* w_q      = (const float*)d_in[3];
    const float* w_k      = (const float*)d_in[4];
    const float* w_v      = (const float*)d_in[5];
    const float* w_fc     = (const float*)d_in[6];
    const float* ln_g     = (const float*)d_in[7];
    const float* ln_b     = (const float*)d_in[8];

    float* x_out = (float*)d_out;                                  // B*DM*E
    float* attn  = x_out + (size_t)B_ * DM_ * E_;                  // B*H*E*E
    float* ape   = attn  + (size_t)B_ * H_ * E_ * E_;              // B*E

    k_transpose<<<dim3(E_ / 32, DM_ / 32, B_), dim3(32, 8)>>>(x);
    k_layernorm<<<B_ * E_, 256>>>(ln_g, ln_b);

    float* dq; cudaGetSymbolAddress((void**)&dq, g_q);
    float* dk; cudaGetSymbolAddress((void**)&dk, g_k);
    float* dv; cudaGetSymbolAddress((void**)&dv, g_v);
    float* ds; cudaGetSymbolAddress((void**)&ds, g_s);
    float* dqn; cudaGetSymbolAddress((void**)&dqn, g_qn);

    k_gemm_qkv<<<dim3(E_ / 64, H_, B_), 256>>>(dqn, w_q, dq, 0.125f);
    k_gemm_qkv<<<dim3(E_ / 64, H_, B_), 256>>>(ds,  w_k, dk, 1.0f);
    k_gemm_qkv<<<dim3(E_ / 64, H_, B_), 256>>>(ds,  w_v, dv, 1.0f);

    k_qr<<<(B_ * H_ * E_ * 6) / 256, 256>>>(base_rpr);
    k_logits<<<dim3(E_ / 64, H_, B_), 256>>>(dist, attn);
    k_softmax<<<B_ * H_ * E_, 256>>>(attn);
    k_ogemm<<<dim3(E_ / 64, H_, B_), 256>>>(attn);
    k_colsum_partial<<<dim3(E_ / 256, B_, 16), 256>>>(dist, attn);
    k_fc<<<dim3(E_ / 64, DM_ / 64, B_), 256>>>(w_fc, x_out);
    k_colsum_final<<<(B_ * E_) / 256, 256>>>(ape);
}

// round 6
// speedup vs baseline: 1.4705x; 1.4705x over previous
#include <cuda_runtime.h>
#include <math.h>

#define B_  2
#define E_  1024
#define DM_ 512
#define H_  8
#define DK_ 64
#define DV_ 64
#define MAXN_ 5
#define NEGV (-1e9f)

__device__ __forceinline__ float tf32q(float x) {
    unsigned u;
    asm("cvt.rna.tf32.f32 %0, %1;" : "=r"(u) : "f"(x));
    return __uint_as_float(u);
}
__device__ __forceinline__ float4 tf32q4(float4 v) {
    v.x = tf32q(v.x); v.y = tf32q(v.y); v.z = tf32q(v.z); v.w = tf32q(v.w);
    return v;
}

// tf32 tensor-core mma: D(16x8) += A(16x8) * B(8x8)
#define MMA8(d, a, b)                                                        \
    asm volatile(                                                            \
        "mma.sync.aligned.m16n8k8.row.col.f32.tf32.tf32.f32 "                \
        "{%0,%1,%2,%3}, {%4,%5,%6,%7}, {%8,%9}, {%0,%1,%2,%3};\n"            \
        : "+f"((d)[0]), "+f"((d)[1]), "+f"((d)[2]), "+f"((d)[3])             \
        : "r"((a)[0]), "r"((a)[1]), "r"((a)[2]), "r"((a)[3]),                \
          "r"((b)[0]), "r"((b)[1]));

// ---------------- scratch ---------------------------------------------------
__device__ float g_s [B_*E_*DM_];
__device__ float g_qn[B_*E_*DM_];
__device__ float g_q [B_*H_*E_*DK_];
__device__ float g_k [B_*H_*E_*DK_];
__device__ float g_v [B_*H_*E_*DV_];
__device__ float g_qr[B_*H_*E_*6];
__device__ float g_o [B_*E_*H_*DV_];
__device__ float g_pcs [16*B_*E_];
__device__ float g_pcnt[16*B_*E_];

// ---------------- 1. transpose x[b,d,e] -> s[b,e,d] ------------------------
__global__ void k_transpose(const float* __restrict__ x) {
    __shared__ float tile[32][33];
    int b = blockIdx.z;
    int e0 = blockIdx.x * 32;
    int d0 = blockIdx.y * 32;
    int tx = threadIdx.x, ty = threadIdx.y;
#pragma unroll
    for (int r = 0; r < 4; r++) {
        int d = d0 + ty + r * 8;
        tile[ty + r * 8][tx] = x[(size_t)b * DM_ * E_ + (size_t)d * E_ + e0 + tx];
    }
    __syncthreads();
#pragma unroll
    for (int r = 0; r < 4; r++) {
        int e = e0 + ty + r * 8;
        g_s[(size_t)b * E_ * DM_ + (size_t)e * DM_ + d0 + tx] = tile[tx][ty + r * 8];
    }
}

// ---------------- 2. LayerNorm ----------------------------------------------
__global__ void k_layernorm(const float* __restrict__ ln_g, const float* __restrict__ ln_b) {
    int row = blockIdx.x;
    const float* src = g_s + (size_t)row * DM_;
    int tid = threadIdx.x;
    float2 v = ((const float2*)src)[tid];
    float s1 = v.x + v.y;
    float s2 = v.x * v.x + v.y * v.y;
#pragma unroll
    for (int o = 16; o; o >>= 1) {
        s1 += __shfl_xor_sync(0xffffffff, s1, o);
        s2 += __shfl_xor_sync(0xffffffff, s2, o);
    }
    __shared__ float sh[16];
    __shared__ float s_mu, s_rstd;
    int w = tid >> 5, l = tid & 31;
    if (l == 0) { sh[w] = s1; sh[8 + w] = s2; }
    __syncthreads();
    if (tid == 0) {
        float a = 0.f, c = 0.f;
#pragma unroll
        for (int i = 0; i < 8; i++) { a += sh[i]; c += sh[8 + i]; }
        float mu  = a / (float)DM_;
        float var = c / (float)DM_ - mu * mu;
        s_mu = mu;
        s_rstd = 1.f / sqrtf(var + 1e-6f);
    }
    __syncthreads();
    float mu = s_mu, rstd = s_rstd;
    float2 gg = ((const float2*)ln_g)[tid];
    float2 bb = ((const float2*)ln_b)[tid];
    float2 o;
    o.x = (v.x - mu) * rstd * gg.x + bb.x;
    o.y = (v.y - mu) * rstd * gg.y + bb.y;
    ((float2*)(g_qn + (size_t)row * DM_))[tid] = o;
}

// ---------------- 3. fused QKV GEMM (tensor core) ---------------------------
// grid (E/128, 24, B): y = mat*8 + h. Block tile 128(M=e) x 64(N=dk), K=512.
__global__ __launch_bounds__(256) void k_qkv_mma(
    const float* __restrict__ A0, const float* __restrict__ A1,
    const float* __restrict__ Wq, const float* __restrict__ Wk,
    const float* __restrict__ Wv)
{
    __shared__ float As[128 * 36];    // stride 36: conflict-free A frags
    __shared__ float Ws[32 * 72];     // stride 72: conflict-free B frags
    int mat = blockIdx.y >> 3, h = blockIdx.y & 7, b = blockIdx.z;
    int m0 = blockIdx.x * 128;
    const float* A = (mat == 0) ? A0 : A1;
    const float* W = (mat == 0) ? Wq : (mat == 1 ? Wk : Wv);
    float* out = (mat == 0) ? g_q : (mat == 1 ? g_k : g_v);
    float scale = (mat == 0) ? 0.125f : 1.0f;

    int tid = threadIdx.x;
    int wid = tid >> 5, lane = tid & 31;
    int g = lane >> 2, t = lane & 3;
    int warpM = wid & 3, warpN = wid >> 2;        // 4 x 2 warps, 32x32 tiles

    const unsigned* Asu = (const unsigned*)As;
    const unsigned* Wsu = (const unsigned*)Ws;
    float acc[2][4][4] = {};
    size_t arow_base = ((size_t)b * E_ + m0);

    for (int k0 = 0; k0 < DM_; k0 += 32) {
        __syncthreads();
#pragma unroll
        for (int i = 0; i < 4; i++) {               // A: 128x32
            int f = tid + i * 256;
            int row = f >> 3, c4 = (f & 7) * 4;
            float4 v = tf32q4(*(const float4*)(A + (arow_base + row) * DM_ + k0 + c4));
            *(float4*)&As[row * 36 + c4] = v;
        }
#pragma unroll
        for (int i = 0; i < 2; i++) {               // W: 32x64
            int f = tid + i * 256;
            int row = f >> 4, c4 = (f & 15) * 4;
            float4 v = tf32q4(*(const float4*)(W + (size_t)(k0 + row) * (H_ * DK_) + h * 64 + c4));
            *(float4*)&Ws[row * 72 + c4] = v;
        }
        __syncthreads();
#pragma unroll
        for (int kk = 0; kk < 4; kk++) {
            int k = kk * 8;
            unsigned af[2][4], bf[4][2];
#pragma unroll
            for (int mb = 0; mb < 2; mb++) {
                int rb = warpM * 32 + mb * 16;
                af[mb][0] = Asu[(rb + g) * 36 + k + t];
                af[mb][1] = Asu[(rb + g + 8) * 36 + k + t];
                af[mb][2] = Asu[(rb + g) * 36 + k + t + 4];
                af[mb][3] = Asu[(rb + g + 8) * 36 + k + t + 4];
            }
#pragma unroll
            for (int nb = 0; nb < 4; nb++) {
                int cb = warpN * 32 + nb * 8 + g;
                bf[nb][0] = Wsu[(k + t) * 72 + cb];
                bf[nb][1] = Wsu[(k + t + 4) * 72 + cb];
            }
#pragma unroll
            for (int mb = 0; mb < 2; mb++)
#pragma unroll
                for (int nb = 0; nb < 4; nb++) MMA8(acc[mb][nb], af[mb], bf[nb])
        }
    }
    // store: out[((b*H+h)*E + e)*64 + dk]
    size_t obase = (((size_t)b * H_ + h) * E_ + m0) * 64;
#pragma unroll
    for (int mb = 0; mb < 2; mb++) {
        int r0 = warpM * 32 + mb * 16 + g;
#pragma unroll
        for (int nb = 0; nb < 4; nb++) {
            int c = warpN * 32 + nb * 8 + 2 * t;
            *(float2*)(out + obase + (size_t)r0 * 64 + c) =
                make_float2(acc[mb][nb][0] * scale, acc[mb][nb][1] * scale);
            *(float2*)(out + obase + (size_t)(r0 + 8) * 64 + c) =
                make_float2(acc[mb][nb][2] * scale, acc[mb][nb][3] * scale);
        }
    }
}

// ---------------- 4. qr table ------------------------------------------------
__global__ void k_qr(const float* __restrict__ base_rpr) {
    __shared__ float rpr[6 * 64];
    int tid = threadIdx.x;
    for (int t = tid; t < 384; t += 256) rpr[t] = tf32q(base_rpr[t]);
    __syncthreads();
    int idx = blockIdx.x * 256 + tid;
    int row = idx / 6, c = idx % 6;
    const float* q = g_q + (size_t)row * DK_;
    float s = 0.f;
#pragma unroll 8
    for (int d = 0; d < DK_; d++) s += tf32q(q[d]) * rpr[c * 64 + d];
    g_qr[(size_t)row * 6 + c] = s;
}

// ---------------- 5. logits (tensor core) ------------------------------------
// grid (E/128, E/64, B*H). Block tile 128(i) x 64(j), K=64 (2 chunks of 32).
__global__ __launch_bounds__(256) void k_logits_mma(
    const int* __restrict__ dist, float* __restrict__ attn)
{
    __shared__ float Qs[128 * 36];
    __shared__ float Ks[64 * 36];
    __shared__ float qrs[128 * 6];
    int z = blockIdx.z, b = z >> 3;
    int i0 = blockIdx.x * 128, j0 = blockIdx.y * 64;
    int tid = threadIdx.x;
    int wid = tid >> 5, lane = tid & 31;
    int g = lane >> 2, t = lane & 3;
    int warpM = wid & 3, warpN = wid >> 2;

    size_t qbase = ((size_t)z * E_ + i0) * 64;
    size_t kbase = ((size_t)z * E_ + j0) * 64;
    for (int tt = tid; tt < 768; tt += 256)
        qrs[tt] = g_qr[((size_t)z * E_ + i0) * 6 + tt];

    const unsigned* Qsu = (const unsigned*)Qs;
    const unsigned* Ksu = (const unsigned*)Ks;
    float acc[2][4][4] = {};

#pragma unroll
    for (int k0 = 0; k0 < 64; k0 += 32) {
        __syncthreads();
#pragma unroll
        for (int i = 0; i < 4; i++) {               // Q: 128x32
            int f = tid + i * 256;
            int row = f >> 3, c4 = (f & 7) * 4;
            float4 v = tf32q4(*(const float4*)(g_q + qbase + (size_t)row * 64 + k0 + c4));
            *(float4*)&Qs[row * 36 + c4] = v;
        }
#pragma unroll
        for (int i = 0; i < 2; i++) {               // K: 64x32
            int f = tid + i * 256;
            int row = f >> 3, c4 = (f & 7) * 4;
            float4 v = tf32q4(*(const float4*)(g_k + kbase + (size_t)row * 64 + k0 + c4));
            *(float4*)&Ks[row * 36 + c4] = v;
        }
        __syncthreads();
#pragma unroll
        for (int kk = 0; kk < 4; kk++) {
            int k = kk * 8;
            unsigned af[2][4], bf[4][2];
#pragma unroll
            for (int mb = 0; mb < 2; mb++) {
                int rb = warpM * 32 + mb * 16;
                af[mb][0] = Qsu[(rb + g) * 36 + k + t];
                af[mb][1] = Qsu[(rb + g + 8) * 36 + k + t];
                af[mb][2] = Qsu[(rb + g) * 36 + k + t + 4];
                af[mb][3] = Qsu[(rb + g + 8) * 36 + k + t + 4];
            }
#pragma unroll
            for (int nb = 0; nb < 4; nb++) {
                int cb = warpN * 32 + nb * 8 + g;    // j row in Ks
                bf[nb][0] = Ksu[cb * 36 + k + t];
                bf[nb][1] = Ksu[cb * 36 + k + t + 4];
            }
#pragma unroll
            for (int mb = 0; mb < 2; mb++)
#pragma unroll
                for (int nb = 0; nb < 4; nb++) MMA8(acc[mb][nb], af[mb], bf[nb])
        }
    }
    // epilogue: + qr[dist], mask, write
    const int* drow = dist + (size_t)b * E_ * E_;
    float* abase = attn + (size_t)z * E_ * E_;
#pragma unroll
    for (int mb = 0; mb < 2; mb++) {
        int il0 = warpM * 32 + mb * 16 + g;
#pragma unroll
        for (int nb = 0; nb < 4; nb++) {
            int jl = warpN * 32 + nb * 8 + 2 * t;
            int j = j0 + jl;
#pragma unroll
            for (int half = 0; half < 2; half++) {
                int il = il0 + half * 8;
                int i = i0 + il;
                int2 dd = *(const int2*)(drow + (size_t)i * E_ + j);
                float c0 = acc[mb][nb][half * 2 + 0];
                float c1 = acc[mb][nb][half * 2 + 1];
                float2 o;
                o.x = (dd.x <= MAXN_) ? c0 + qrs[il * 6 + dd.x] : NEGV;
                o.y = (dd.y <= MAXN_) ? c1 + qrs[il * 6 + dd.y] : NEGV;
                *(float2*)(abase + (size_t)i * E_ + j) = o;
            }
        }
    }
}

// ---------------- 6. row softmax (in place) ----------------------------------
__global__ void k_softmax(float* __restrict__ attn) {
    size_t base = (size_t)blockIdx.x * E_;
    int tid = threadIdx.x;
    float4 v = ((float4*)(attn + base))[tid];
    float m = fmaxf(fmaxf(v.x, v.y), fmaxf(v.z, v.w));
#pragma unroll
    for (int o = 16; o; o >>= 1) m = fmaxf(m, __shfl_xor_sync(0xffffffff, m, o));
    __shared__ float sh[8];
    __shared__ float s_m, s_inv;
    int w = tid >> 5, l = tid & 31;
    if (l == 0) sh[w] = m;
    __syncthreads();
    if (tid == 0) {
        float mm = sh[0];
#pragma unroll
        for (int i = 1; i < 8; i++) mm = fmaxf(mm, sh[i]);
        s_m = mm;
    }
    __syncthreads();
    m = s_m;
    v.x = expf(v.x - m); v.y = expf(v.y - m);
    v.z = expf(v.z - m); v.w = expf(v.w - m);
    float s = v.x + v.y + v.z + v.w;
#pragma unroll
    for (int o = 16; o; o >>= 1) s += __shfl_xor_sync(0xffffffff, s, o);
    if (l == 0) sh[w] = s;
    __syncthreads();
    if (tid == 0) {
        float ss = 0.f;
#pragma unroll
        for (int i = 0; i < 8; i++) ss += sh[i];
        s_inv = 1.f / ss;
    }
    __syncthreads();
    float inv = s_inv;
    v.x *= inv; v.y *= inv; v.z *= inv; v.w *= inv;
    ((float4*)(attn + base))[tid] = v;
}

// ---------------- 7. O = attn @ V (tensor core) -------------------------------
// grid (E/128, 1, B*H). Block tile 128(i) x 64(d), K=1024 in 32-chunks.
__global__ __launch_bounds__(256) void k_ogemm_mma(const float* __restrict__ attn) {
    __shared__ float Ps[128 * 36];
    __shared__ float Vs[32 * 72];
    int z = blockIdx.z, b = z >> 3, h = z & 7;
    int i0 = blockIdx.x * 128;
    int tid = threadIdx.x;
    int wid = tid >> 5, lane = tid & 31;
    int g = lane >> 2, t = lane & 3;
    int warpM = wid & 3, warpN = wid >> 2;

    const float* abase = attn + ((size_t)z * E_ + i0) * E_;
    const float* vbase = g_v + (size_t)z * E_ * 64;
    const unsigned* Psu = (const unsigned*)Ps;
    const unsigned* Vsu = (const unsigned*)Vs;
    float acc[2][4][4] = {};

    for (int k0 = 0; k0 < E_; k0 += 32) {
        __syncthreads();
#pragma unroll
        for (int i = 0; i < 4; i++) {               // attn: 128x32
            int f = tid + i * 256;
            int row = f >> 3, c4 = (f & 7) * 4;
            float4 v = tf32q4(*(const float4*)(abase + (size_t)row * E_ + k0 + c4));
            *(float4*)&Ps[row * 36 + c4] = v;
        }
#pragma unroll
        for (int i = 0; i < 2; i++) {               // V: 32x64
            int f = tid + i * 256;
            int row = f >> 4, c4 = (f & 15) * 4;
            float4 v = tf32q4(*(const float4*)(vbase + (size_t)(k0 + row) * 64 + c4));
            *(float4*)&Vs[row * 72 + c4] = v;
        }
        __syncthreads();
#pragma unroll
        for (int kk = 0; kk < 4; kk++) {
            int k = kk * 8;
            unsigned af[2][4], bf[4][2];
#pragma unroll
            for (int mb = 0; mb < 2; mb++) {
                int rb = warpM * 32 + mb * 16;
                af[mb][0] = Psu[(rb + g) * 36 + k + t];
                af[mb][1] = Psu[(rb + g + 8) * 36 + k + t];
                af[mb][2] = Psu[(rb + g) * 36 + k + t + 4];
                af[mb][3] = Psu[(rb + g + 8) * 36 + k + t + 4];
            }
#pragma unroll
            for (int nb = 0; nb < 4; nb++) {
                int cb = warpN * 32 + nb * 8 + g;
                bf[nb][0] = Vsu[(k + t) * 72 + cb];
                bf[nb][1] = Vsu[(k + t + 4) * 72 + cb];
            }
#pragma unroll
            for (int mb = 0; mb < 2; mb++)
#pragma unroll
                for (int nb = 0; nb < 4; nb++) MMA8(acc[mb][nb], af[mb], bf[nb])
        }
    }
    // store g_o[(b*E + i)*512 + h*64 + d]
#pragma unroll
    for (int mb = 0; mb < 2; mb++) {
        int r0 = warpM * 32 + mb * 16 + g;
#pragma unroll
        for (int nb = 0; nb < 4; nb++) {
            int c = h * 64 + warpN * 32 + nb * 8 + 2 * t;
            *(float2*)(g_o + ((size_t)b * E_ + i0 + r0) * 512 + c) =
                make_float2(acc[mb][nb][0], acc[mb][nb][1]);
            *(float2*)(g_o + ((size_t)b * E_ + i0 + r0 + 8) * 512 + c) =
                make_float2(acc[mb][nb][2], acc[mb][nb][3]);
        }
    }
}

// ---------------- 8. FC + residual + transposed store (tensor core) ----------
// grid (B*E/128, DM/64). Block tile 128(row=b*E+e) x 64(n), K=512.
__global__ __launch_bounds__(256) void k_fc_mma(
    const float* __restrict__ w_fc, float* __restrict__ xout)
{
    __shared__ float sm[64 * 132];     // union: (As 128*36 | Ws 32*72) then stageT
    float* As = sm;
    float* Ws = sm + 128 * 36;
    int m0 = blockIdx.x * 128, n0 = blockIdx.y * 64;
    int b = m0 >> 10, e0 = m0 & 1023;
    int tid = threadIdx.x;
    int wid = tid >> 5, lane = tid & 31;
    int g = lane >> 2, t = lane & 3;
    int warpM = wid & 3, warpN = wid >> 2;

    const unsigned* Asu = (const unsigned*)As;
    const unsigned* Wsu = (const unsigned*)Ws;
    float acc[2][4][4] = {};

    for (int k0 = 0; k0 < 512; k0 += 32) {
        __syncthreads();
#pragma unroll
        for (int i = 0; i < 4; i++) {               // g_o: 128x32
            int f = tid + i * 256;
            int row = f >> 3, c4 = (f & 7) * 4;
            float4 v = tf32q4(*(const float4*)(g_o + (size_t)(m0 + row) * 512 + k0 + c4));
            *(float4*)&As[row * 36 + c4] = v;
        }
#pragma unroll
        for (int i = 0; i < 2; i++) {               // w_fc: 32x64
            int f = tid + i * 256;
            int row = f >> 4, c4 = (f & 15) * 4;
            float4 v = tf32q4(*(const float4*)(w_fc + (size_t)(k0 + row) * DM_ + n0 + c4));
            *(float4*)&Ws[row * 72 + c4] = v;
        }
        __syncthreads();
#pragma unroll
        for (int kk = 0; kk < 4; kk++) {
            int k = kk * 8;
            unsigned af[2][4], bf[4][2];
#pragma unroll
            for (int mb = 0; mb < 2; mb++) {
                int rb = warpM * 32 + mb * 16;
                af[mb][0] = Asu[(rb + g) * 36 + k + t];
                af[mb][1] = Asu[(rb + g + 8) * 36 + k + t];
                af[mb][2] = Asu[(rb + g) * 36 + k + t + 4];
                af[mb][3] = Asu[(rb + g + 8) * 36 + k + t + 4];
            }
#pragma unroll
            for (int nb = 0; nb < 4; nb++) {
                int cb = warpN * 32 + nb * 8 + g;
                bf[nb][0] = Wsu[(k + t) * 72 + cb];
                bf[nb][1] = Wsu[(k + t + 4) * 72 + cb];
            }
#pragma unroll
            for (int mb = 0; mb < 2; mb++)
#pragma unroll
                for (int nb = 0; nb < 4; nb++) MMA8(acc[mb][nb], af[mb], bf[nb])
        }
    }
    // stage transposed (+ residual): stageT[n_loc][e_loc], stride 132
    __syncthreads();
#pragma unroll
    for (int mb = 0; mb < 2; mb++) {
        int el0 = warpM * 32 + mb * 16 + g;
#pragma unroll
        for (int nb = 0; nb < 4; nb++) {
            int nl = warpN * 32 + nb * 8 + 2 * t;
#pragma unroll
            for (int half = 0; half < 2; half++) {
                int el = el0 + half * 8;
                const float* res = g_s + (size_t)(m0 + el) * DM_ + n0 + nl;
                sm[(nl + 0) * 132 + el] = acc[mb][nb][half * 2 + 0] + res[0];
                sm[(nl + 1) * 132 + el] = acc[mb][nb][half * 2 + 1] + res[1];
            }
        }
    }
    __syncthreads();
    // write xout[b][n][e]: 64 rows x 128 cols
#pragma unroll
    for (int i = 0; i < 8; i++) {
        int f = tid + i * 256;
        int row = f >> 5, c4 = (f & 31) * 4;
        float4 v = *(const float4*)&sm[row * 132 + c4];
        *(float4*)(xout + ((size_t)b * DM_ + n0 + row) * E_ + e0 + c4) = v;
    }
}

// ---------------- 9. attn_per_edge column sums --------------------------------
__global__ void k_colsum_partial(const int* __restrict__ dist,
                                 const float* __restrict__ attn)
{
    int j = blockIdx.x * 256 + threadIdx.x;
    int b = blockIdx.y, z = blockIdx.z;
    float cs = 0.f, cn = 0.f;
    for (int i = z * 64; i < z * 64 + 64; i++) {
        int dv = dist[(size_t)b * E_ * E_ + (size_t)i * E_ + j];
        if (dv <= MAXN_) {
            cn += 1.f;
#pragma unroll
            for (int h = 0; h < H_; h++)
                cs += attn[(((size_t)b * H_ + h) * E_ + i) * E_ + j];
        }
    }
    g_pcs [((size_t)z * B_ + b) * E_ + j] = cs;
    g_pcnt[((size_t)z * B_ + b) * E_ + j] = cn;
}

__global__ void k_colsum_final(float* __restrict__ ape) {
    int idx = blockIdx.x * 256 + threadIdx.x;
    int b = idx >> 10, j = idx & (E_ - 1);
    float cs = 0.f, cn = 0.f;
#pragma unroll
    for (int z = 0; z < 16; z++) {
        cs += g_pcs [((size_t)z * B_ + b) * E_ + j];
        cn += g_pcnt[((size_t)z * B_ + b) * E_ + j];
    }
    ape[idx] = cs / cn;   // denominator: mask count only (size-1 head axis)
}

// ---------------- launch ------------------------------------------------------
extern "C" void kernel_launch(void* const* d_in, const int* in_sizes, int n_in,
                              void* d_out, int out_size) {
    const float* x        = (const float*)d_in[0];
    const int*   dist     = (const int*)  d_in[1];
    const float* base_rpr = (const float*)d_in[2];
    const float* w_q      = (const float*)d_in[3];
    const float* w_k      = (const float*)d_in[4];
    const float* w_v      = (const float*)d_in[5];
    const float* w_fc     = (const float*)d_in[6];
    const float* ln_g     = (const float*)d_in[7];
    const float* ln_b     = (const float*)d_in[8];

    float* x_out = (float*)d_out;
    float* attn  = x_out + (size_t)B_ * DM_ * E_;
    float* ape   = attn  + (size_t)B_ * H_ * E_ * E_;

    float* ds;  cudaGetSymbolAddress((void**)&ds,  g_s);
    float* dqn; cudaGetSymbolAddress((void**)&dqn, g_qn);

    k_transpose<<<dim3(E_ / 32, DM_ / 32, B_), dim3(32, 8)>>>(x);
    k_layernorm<<<B_ * E_, 256>>>(ln_g, ln_b);

    k_qkv_mma<<<dim3(E_ / 128, 24, B_), 256>>>(dqn, ds, w_q, w_k, w_v);
    k_qr<<<(B_ * H_ * E_ * 6) / 256, 256>>>(base_rpr);

    k_logits_mma<<<dim3(E_ / 128, E_ / 64, B_ * H_), 256>>>(dist, attn);
    k_softmax<<<B_ * H_ * E_, 256>>>(attn);
    k_ogemm_mma<<<dim3(E_ / 128, 1, B_ * H_), 256>>>(attn);
    k_colsum_partial<<<dim3(E_ / 256, B_, 16), 256>>>(dist, attn);
    k_fc_mma<<<dim3(B_ * E_ / 128, DM_ / 64, 1), 256>>>(w_fc, x_out);
    k_colsum_final<<<(B_ * E_) / 256, 256>>>(ape);
}

// round 7
// speedup vs baseline: 1.6934x; 1.1515x over previous
#include <cuda_runtime.h>
#include <math.h>

#define B_  2
#define E_  1024
#define DM_ 512
#define H_  8
#define DK_ 64
#define DV_ 64
#define MAXN_ 5
#define NEGV (-1e9f)

__device__ __forceinline__ float tf32q(float x) {
    unsigned u;
    asm("cvt.rna.tf32.f32 %0, %1;" : "=r"(u) : "f"(x));
    return __uint_as_float(u);
}
__device__ __forceinline__ float4 tf32q4(float4 v) {
    v.x = tf32q(v.x); v.y = tf32q(v.y); v.z = tf32q(v.z); v.w = tf32q(v.w);
    return v;
}

// tf32 tensor-core mma: D(16x8) += A(16x8) * B(8x8)
#define MMA8(d, a, b)                                                        \
    asm volatile(                                                            \
        "mma.sync.aligned.m16n8k8.row.col.f32.tf32.tf32.f32 "                \
        "{%0,%1,%2,%3}, {%4,%5,%6,%7}, {%8,%9}, {%0,%1,%2,%3};\n"            \
        : "+f"((d)[0]), "+f"((d)[1]), "+f"((d)[2]), "+f"((d)[3])             \
        : "r"((a)[0]), "r"((a)[1]), "r"((a)[2]), "r"((a)[3]),                \
          "r"((b)[0]), "r"((b)[1]));

// ---------------- scratch ---------------------------------------------------
__device__ float g_s [B_*E_*DM_];
__device__ float g_qn[B_*E_*DM_];
__device__ float g_q [B_*H_*E_*DK_];
__device__ float g_k [B_*H_*E_*DK_];
__device__ float g_v [B_*H_*E_*DV_];
__device__ float g_qr[B_*H_*E_*6];
__device__ float g_o [B_*E_*H_*DV_];
__device__ float g_pcs2[B_*H_*16*E_];   // per (z, i-block) column partial sums

// ---------------- 1. transpose x[b,d,e] -> s[b,e,d] ------------------------
__global__ void k_transpose(const float* __restrict__ x) {
    __shared__ float tile[32][33];
    int b = blockIdx.z;
    int e0 = blockIdx.x * 32;
    int d0 = blockIdx.y * 32;
    int tx = threadIdx.x, ty = threadIdx.y;
#pragma unroll
    for (int r = 0; r < 4; r++) {
        int d = d0 + ty + r * 8;
        tile[ty + r * 8][tx] = x[(size_t)b * DM_ * E_ + (size_t)d * E_ + e0 + tx];
    }
    __syncthreads();
#pragma unroll
    for (int r = 0; r < 4; r++) {
        int e = e0 + ty + r * 8;
        g_s[(size_t)b * E_ * DM_ + (size_t)e * DM_ + d0 + tx] = tile[tx][ty + r * 8];
    }
}

// ---------------- 2. LayerNorm ----------------------------------------------
__global__ void k_layernorm(const float* __restrict__ ln_g, const float* __restrict__ ln_b) {
    int row = blockIdx.x;
    const float* src = g_s + (size_t)row * DM_;
    int tid = threadIdx.x;
    float2 v = ((const float2*)src)[tid];
    float s1 = v.x + v.y;
    float s2 = v.x * v.x + v.y * v.y;
#pragma unroll
    for (int o = 16; o; o >>= 1) {
        s1 += __shfl_xor_sync(0xffffffff, s1, o);
        s2 += __shfl_xor_sync(0xffffffff, s2, o);
    }
    __shared__ float sh[16];
    __shared__ float s_mu, s_rstd;
    int w = tid >> 5, l = tid & 31;
    if (l == 0) { sh[w] = s1; sh[8 + w] = s2; }
    __syncthreads();
    if (tid == 0) {
        float a = 0.f, c = 0.f;
#pragma unroll
        for (int i = 0; i < 8; i++) { a += sh[i]; c += sh[8 + i]; }
        float mu  = a / (float)DM_;
        float var = c / (float)DM_ - mu * mu;
        s_mu = mu;
        s_rstd = 1.f / sqrtf(var + 1e-6f);
    }
    __syncthreads();
    float mu = s_mu, rstd = s_rstd;
    float2 gg = ((const float2*)ln_g)[tid];
    float2 bb = ((const float2*)ln_b)[tid];
    float2 o;
    o.x = (v.x - mu) * rstd * gg.x + bb.x;
    o.y = (v.y - mu) * rstd * gg.y + bb.y;
    ((float2*)(g_qn + (size_t)row * DM_))[tid] = o;
}

// ---------------- 3. fused QKV GEMM (tensor core) ---------------------------
__global__ __launch_bounds__(256) void k_qkv_mma(
    const float* __restrict__ A0, const float* __restrict__ A1,
    const float* __restrict__ Wq, const float* __restrict__ Wk,
    const float* __restrict__ Wv)
{
    __shared__ float As[128 * 36];
    __shared__ float Ws[32 * 72];
    int mat = blockIdx.y >> 3, h = blockIdx.y & 7, b = blockIdx.z;
    int m0 = blockIdx.x * 128;
    const float* A = (mat == 0) ? A0 : A1;
    const float* W = (mat == 0) ? Wq : (mat == 1 ? Wk : Wv);
    float* out = (mat == 0) ? g_q : (mat == 1 ? g_k : g_v);
    float scale = (mat == 0) ? 0.125f : 1.0f;

    int tid = threadIdx.x;
    int wid = tid >> 5, lane = tid & 31;
    int g = lane >> 2, t = lane & 3;
    int warpM = wid & 3, warpN = wid >> 2;

    const unsigned* Asu = (const unsigned*)As;
    const unsigned* Wsu = (const unsigned*)Ws;
    float acc[2][4][4] = {};
    size_t arow_base = ((size_t)b * E_ + m0);

    for (int k0 = 0; k0 < DM_; k0 += 32) {
        __syncthreads();
#pragma unroll
        for (int i = 0; i < 4; i++) {
            int f = tid + i * 256;
            int row = f >> 3, c4 = (f & 7) * 4;
            float4 v = tf32q4(*(const float4*)(A + (arow_base + row) * DM_ + k0 + c4));
            *(float4*)&As[row * 36 + c4] = v;
        }
#pragma unroll
        for (int i = 0; i < 2; i++) {
            int f = tid + i * 256;
            int row = f >> 4, c4 = (f & 15) * 4;
            float4 v = tf32q4(*(const float4*)(W + (size_t)(k0 + row) * (H_ * DK_) + h * 64 + c4));
            *(float4*)&Ws[row * 72 + c4] = v;
        }
        __syncthreads();
#pragma unroll
        for (int kk = 0; kk < 4; kk++) {
            int k = kk * 8;
            unsigned af[2][4], bf[4][2];
#pragma unroll
            for (int mb = 0; mb < 2; mb++) {
                int rb = warpM * 32 + mb * 16;
                af[mb][0] = Asu[(rb + g) * 36 + k + t];
                af[mb][1] = Asu[(rb + g + 8) * 36 + k + t];
                af[mb][2] = Asu[(rb + g) * 36 + k + t + 4];
                af[mb][3] = Asu[(rb + g + 8) * 36 + k + t + 4];
            }
#pragma unroll
            for (int nb = 0; nb < 4; nb++) {
                int cb = warpN * 32 + nb * 8 + g;
                bf[nb][0] = Wsu[(k + t) * 72 + cb];
                bf[nb][1] = Wsu[(k + t + 4) * 72 + cb];
            }
#pragma unroll
            for (int mb = 0; mb < 2; mb++)
#pragma unroll
                for (int nb = 0; nb < 4; nb++) MMA8(acc[mb][nb], af[mb], bf[nb])
        }
    }
    size_t obase = (((size_t)b * H_ + h) * E_ + m0) * 64;
#pragma unroll
    for (int mb = 0; mb < 2; mb++) {
        int r0 = warpM * 32 + mb * 16 + g;
#pragma unroll
        for (int nb = 0; nb < 4; nb++) {
            int c = warpN * 32 + nb * 8 + 2 * t;
            *(float2*)(out + obase + (size_t)r0 * 64 + c) =
                make_float2(acc[mb][nb][0] * scale, acc[mb][nb][1] * scale);
            *(float2*)(out + obase + (size_t)(r0 + 8) * 64 + c) =
                make_float2(acc[mb][nb][2] * scale, acc[mb][nb][3] * scale);
        }
    }
}

// ---------------- 4. qr table (smem-staged, coalesced) -----------------------
// grid 512 blocks x 256 threads; each block: 32 rows
__global__ void k_qr(const float* __restrict__ base_rpr) {
    __shared__ float rpr[384];
    __shared__ float qs[32 * 65];
    int tid = threadIdx.x;
    for (int t = tid; t < 384; t += 256) rpr[t] = tf32q(base_rpr[t]);
    size_t r0 = (size_t)blockIdx.x * 32;
#pragma unroll
    for (int i = 0; i < 8; i++) {
        int f = tid + i * 256;            // 2048 floats = 32 rows x 64
        int row = f >> 6, col = f & 63;
        qs[row * 65 + col] = tf32q(g_q[(r0 + row) * 64 + col]);
    }
    __syncthreads();
    if (tid < 192) {
        int row = tid / 6, c = tid % 6;
        float s = 0.f;
#pragma unroll 16
        for (int d = 0; d < 64; d++) s += qs[row * 65 + d] * rpr[c * 64 + d];
        g_qr[(r0 + row) * 6 + c] = s;
    }
}

// ---------------- 5. fused logits + softmax + colsum partials ----------------
// grid (E/64, B*H), 256 threads. Block owns 64 full rows of one (b,h).
__global__ __launch_bounds__(256) void k_attn_fused(
    const int* __restrict__ dist, float* __restrict__ attn)
{
    __shared__ float Qs[2][64 * 36];
    __shared__ float Ks[2][64 * 36];
    __shared__ float qrs[64 * 6];
    __shared__ float rowm[64][4], rowl[64][4];
    __shared__ float mfin[64], lfin[64];

    int z = blockIdx.y, b = z >> 3;
    int iblk = blockIdx.x, i0 = iblk * 64;
    int tid = threadIdx.x, wid = tid >> 5, lane = tid & 31;
    int g = lane >> 2, t = lane & 3;
    int warpM = wid & 1, warpN = wid >> 1;      // 2 x 4 warps: 32-row x 16-col tiles

    size_t qbase = ((size_t)z * E_ + i0) * 64;
#pragma unroll
    for (int c = 0; c < 2; c++)
#pragma unroll
        for (int i = 0; i < 2; i++) {
            int f = tid + i * 256;              // 512 float4 per 32-col chunk
            int row = f >> 3, c4 = (f & 7) * 4;
            float4 v = tf32q4(*(const float4*)(g_q + qbase + (size_t)row * 64 + c * 32 + c4));
            *(float4*)&Qs[c][row * 36 + c4] = v;
        }
    for (int tt = tid; tt < 384; tt += 256)
        qrs[tt] = g_qr[((size_t)z * E_ + i0) * 6 + tt];

    const int* drow = dist + (size_t)b * E_ * E_;
    float* abase = attn + (size_t)z * E_ * E_ + (size_t)i0 * E_;

    float m[4], l[4];
#pragma unroll
    for (int r = 0; r < 4; r++) { m[r] = -3.0e38f; l[r] = 0.f; }

    for (int jt = 0; jt < 16; jt++) {
        int j0 = jt * 64;
        size_t kbase = ((size_t)z * E_ + j0) * 64;
        __syncthreads();
#pragma unroll
        for (int c = 0; c < 2; c++)
#pragma unroll
            for (int i = 0; i < 2; i++) {
                int f = tid + i * 256;
                int row = f >> 3, c4 = (f & 7) * 4;
                float4 v = tf32q4(*(const float4*)(g_k + kbase + (size_t)row * 64 + c * 32 + c4));
                *(float4*)&Ks[c][row * 36 + c4] = v;
            }
        __syncthreads();
        float acc[2][2][4] = {};
#pragma unroll
        for (int c = 0; c < 2; c++) {
            const unsigned* Qsu = (const unsigned*)Qs[c];
            const unsigned* Ksu = (const unsigned*)Ks[c];
#pragma unroll
            for (int kk = 0; kk < 4; kk++) {
                int k = kk * 8;
                unsigned af[2][4], bf[2][2];
#pragma unroll
                for (int mb = 0; mb < 2; mb++) {
                    int rb = warpM * 32 + mb * 16;
                    af[mb][0] = Qsu[(rb + g) * 36 + k + t];
                    af[mb][1] = Qsu[(rb + g + 8) * 36 + k + t];
                    af[mb][2] = Qsu[(rb + g) * 36 + k + t + 4];
                    af[mb][3] = Qsu[(rb + g + 8) * 36 + k + t + 4];
                }
#pragma unroll
                for (int nb = 0; nb < 2; nb++) {
                    int cb = warpN * 16 + nb * 8 + g;
                    bf[nb][0] = Ksu[cb * 36 + k + t];
                    bf[nb][1] = Ksu[cb * 36 + k + t + 4];
                }
#pragma unroll
                for (int mb = 0; mb < 2; mb++)
#pragma unroll
                    for (int nb = 0; nb < 2; nb++) MMA8(acc[mb][nb], af[mb], bf[nb])
            }
        }
        // epilogue: qr/mask, write raw logits, online (m,l)
#pragma unroll
        for (int mb = 0; mb < 2; mb++)
#pragma unroll
            for (int half = 0; half < 2; half++) {
                int il = warpM * 32 + mb * 16 + half * 8 + g;
                int r = mb * 2 + half;
#pragma unroll
                for (int nb = 0; nb < 2; nb++) {
                    int j = j0 + warpN * 16 + nb * 8 + 2 * t;
                    int2 dd = *(const int2*)(drow + (size_t)(i0 + il) * E_ + j);
                    float x0 = (dd.x <= MAXN_) ? acc[mb][nb][half * 2 + 0] + qrs[il * 6 + dd.x] : NEGV;
                    float x1 = (dd.y <= MAXN_) ? acc[mb][nb][half * 2 + 1] + qrs[il * 6 + dd.y] : NEGV;
                    *(float2*)(abase + (size_t)il * E_ + j) = make_float2(x0, x1);
                    float nm = fmaxf(m[r], fmaxf(x0, x1));
                    l[r] = l[r] * __expf(m[r] - nm) + __expf(x0 - nm) + __expf(x1 - nm);
                    m[r] = nm;
                }
            }
    }
    // reduce (m,l) over the 4 t-lanes
#pragma unroll
    for (int r = 0; r < 4; r++)
#pragma unroll
        for (int off = 1; off < 4; off <<= 1) {
            float om = __shfl_xor_sync(0xffffffff, m[r], off);
            float ol = __shfl_xor_sync(0xffffffff, l[r], off);
            float nm = fmaxf(m[r], om);
            l[r] = l[r] * __expf(m[r] - nm) + ol * __expf(om - nm);
            m[r] = nm;
        }
    if (t == 0) {
#pragma unroll
        for (int mb = 0; mb < 2; mb++)
#pragma unroll
            for (int half = 0; half < 2; half++) {
                int il = warpM * 32 + mb * 16 + half * 8 + g;
                int r = mb * 2 + half;
                rowm[il][warpN] = m[r];
                rowl[il][warpN] = l[r];
            }
    }
    __syncthreads();
    if (tid < 64) {
        float mm = rowm[tid][0], ll = rowl[tid][0];
#pragma unroll
        for (int w = 1; w < 4; w++) {
            float om = rowm[tid][w], ol = rowl[tid][w];
            float nm = fmaxf(mm, om);
            ll = ll * __expf(mm - nm) + ol * __expf(om - nm);
            mm = nm;
        }
        mfin[tid] = mm;
        lfin[tid] = 1.f / ll;
    }
    __syncthreads();
    // pass B: normalize in place + column partial sums (masked entries are 0)
    float4 cs = make_float4(0.f, 0.f, 0.f, 0.f);
#pragma unroll 4
    for (int i = 0; i < 64; i++) {
        float mm = mfin[i], li = lfin[i];
        float4 x = *(float4*)(abase + (size_t)i * E_ + tid * 4);
        x.x = __expf(x.x - mm) * li; x.y = __expf(x.y - mm) * li;
        x.z = __expf(x.z - mm) * li; x.w = __expf(x.w - mm) * li;
        *(float4*)(abase + (size_t)i * E_ + tid * 4) = x;
        cs.x += x.x; cs.y += x.y; cs.z += x.z; cs.w += x.w;
    }
    *(float4*)(g_pcs2 + ((size_t)z * 16 + iblk) * E_ + tid * 4) = cs;
}

// ---------------- 6. O = attn @ V (tensor core) -------------------------------
__global__ __launch_bounds__(256) void k_ogemm_mma(const float* __restrict__ attn) {
    __shared__ float Ps[128 * 36];
    __shared__ float Vs[32 * 72];
    int z = blockIdx.z, b = z >> 3, h = z & 7;
    int i0 = blockIdx.x * 128;
    int tid = threadIdx.x;
    int wid = tid >> 5, lane = tid & 31;
    int g = lane >> 2, t = lane & 3;
    int warpM = wid & 3, warpN = wid >> 2;

    const float* abase = attn + ((size_t)z * E_ + i0) * E_;
    const float* vbase = g_v + (size_t)z * E_ * 64;
    const unsigned* Psu = (const unsigned*)Ps;
    const unsigned* Vsu = (const unsigned*)Vs;
    float acc[2][4][4] = {};

    for (int k0 = 0; k0 < E_; k0 += 32) {
        __syncthreads();
#pragma unroll
        for (int i = 0; i < 4; i++) {
            int f = tid + i * 256;
            int row = f >> 3, c4 = (f & 7) * 4;
            float4 v = tf32q4(*(const float4*)(abase + (size_t)row * E_ + k0 + c4));
            *(float4*)&Ps[row * 36 + c4] = v;
        }
#pragma unroll
        for (int i = 0; i < 2; i++) {
            int f = tid + i * 256;
            int row = f >> 4, c4 = (f & 15) * 4;
            float4 v = tf32q4(*(const float4*)(vbase + (size_t)(k0 + row) * 64 + c4));
            *(float4*)&Vs[row * 72 + c4] = v;
        }
        __syncthreads();
#pragma unroll
        for (int kk = 0; kk < 4; kk++) {
            int k = kk * 8;
            unsigned af[2][4], bf[4][2];
#pragma unroll
            for (int mb = 0; mb < 2; mb++) {
                int rb = warpM * 32 + mb * 16;
                af[mb][0] = Psu[(rb + g) * 36 + k + t];
                af[mb][1] = Psu[(rb + g + 8) * 36 + k + t];
                af[mb][2] = Psu[(rb + g) * 36 + k + t + 4];
                af[mb][3] = Psu[(rb + g + 8) * 36 + k + t + 4];
            }
#pragma unroll
            for (int nb = 0; nb < 4; nb++) {
                int cb = warpN * 32 + nb * 8 + g;
                bf[nb][0] = Vsu[(k + t) * 72 + cb];
                bf[nb][1] = Vsu[(k + t + 4) * 72 + cb];
            }
#pragma unroll
            for (int mb = 0; mb < 2; mb++)
#pragma unroll
                for (int nb = 0; nb < 4; nb++) MMA8(acc[mb][nb], af[mb], bf[nb])
        }
    }
#pragma unroll
    for (int mb = 0; mb < 2; mb++) {
        int r0 = warpM * 32 + mb * 16 + g;
#pragma unroll
        for (int nb = 0; nb < 4; nb++) {
            int c = h * 64 + warpN * 32 + nb * 8 + 2 * t;
            *(float2*)(g_o + ((size_t)b * E_ + i0 + r0) * 512 + c) =
                make_float2(acc[mb][nb][0], acc[mb][nb][1]);
            *(float2*)(g_o + ((size_t)b * E_ + i0 + r0 + 8) * 512 + c) =
                make_float2(acc[mb][nb][2], acc[mb][nb][3]);
        }
    }
}

// ---------------- 7. FC + residual + transposed store (tensor core) ----------
__global__ __launch_bounds__(256) void k_fc_mma(
    const float* __restrict__ w_fc, float* __restrict__ xout)
{
    __shared__ float sm[64 * 132];
    float* As = sm;
    float* Ws = sm + 128 * 36;
    int m0 = blockIdx.x * 128, n0 = blockIdx.y * 64;
    int b = m0 >> 10, e0 = m0 & 1023;
    int tid = threadIdx.x;
    int wid = tid >> 5, lane = tid & 31;
    int g = lane >> 2, t = lane & 3;
    int warpM = wid & 3, warpN = wid >> 2;

    const unsigned* Asu = (const unsigned*)As;
    const unsigned* Wsu = (const unsigned*)Ws;
    float acc[2][4][4] = {};

    for (int k0 = 0; k0 < 512; k0 += 32) {
        __syncthreads();
#pragma unroll
        for (int i = 0; i < 4; i++) {
            int f = tid + i * 256;
            int row = f >> 3, c4 = (f & 7) * 4;
            float4 v = tf32q4(*(const float4*)(g_o + (size_t)(m0 + row) * 512 + k0 + c4));
            *(float4*)&As[row * 36 + c4] = v;
        }
#pragma unroll
        for (int i = 0; i < 2; i++) {
            int f = tid + i * 256;
            int row = f >> 4, c4 = (f & 15) * 4;
            float4 v = tf32q4(*(const float4*)(w_fc + (size_t)(k0 + row) * DM_ + n0 + c4));
            *(float4*)&Ws[row * 72 + c4] = v;
        }
        __syncthreads();
#pragma unroll
        for (int kk = 0; kk < 4; kk++) {
            int k = kk * 8;
            unsigned af[2][4], bf[4][2];
#pragma unroll
            for (int mb = 0; mb < 2; mb++) {
                int rb = warpM * 32 + mb * 16;
                af[mb][0] = Asu[(rb + g) * 36 + k + t];
                af[mb][1] = Asu[(rb + g + 8) * 36 + k + t];
                af[mb][2] = Asu[(rb + g) * 36 + k + t + 4];
                af[mb][3] = Asu[(rb + g + 8) * 36 + k + t + 4];
            }
#pragma unroll
            for (int nb = 0; nb < 4; nb++) {
                int cb = warpN * 32 + nb * 8 + g;
                bf[nb][0] = Wsu[(k + t) * 72 + cb];
                bf[nb][1] = Wsu[(k + t + 4) * 72 + cb];
            }
#pragma unroll
            for (int mb = 0; mb < 2; mb++)
#pragma unroll
                for (int nb = 0; nb < 4; nb++) MMA8(acc[mb][nb], af[mb], bf[nb])
        }
    }
    __syncthreads();
#pragma unroll
    for (int mb = 0; mb < 2; mb++) {
        int el0 = warpM * 32 + mb * 16 + g;
#pragma unroll
        for (int nb = 0; nb < 4; nb++) {
            int nl = warpN * 32 + nb * 8 + 2 * t;
#pragma unroll
            for (int half = 0; half < 2; half++) {
                int el = el0 + half * 8;
                const float* res = g_s + (size_t)(m0 + el) * DM_ + n0 + nl;
                sm[(nl + 0) * 132 + el] = acc[mb][nb][half * 2 + 0] + res[0];
                sm[(nl + 1) * 132 + el] = acc[mb][nb][half * 2 + 1] + res[1];
            }
        }
    }
    __syncthreads();
#pragma unroll
    for (int i = 0; i < 8; i++) {
        int f = tid + i * 256;
        int row = f >> 5, c4 = (f & 31) * 4;
        float4 v = *(const float4*)&sm[row * 132 + c4];
        *(float4*)(xout + ((size_t)b * DM_ + n0 + row) * E_ + e0 + c4) = v;
    }
}

// ---------------- 8. ape final: combine partials + mask counts ----------------
__global__ void k_ape_final(const int* __restrict__ dist, float* __restrict__ ape) {
    int idx = blockIdx.x * 256 + threadIdx.x;   // 0 .. B*E-1
    int b = idx >> 10, j = idx & (E_ - 1);
    float cs = 0.f;
    const float* p = g_pcs2 + (size_t)b * 8 * 16 * E_ + j;
#pragma unroll 8
    for (int k = 0; k < 128; k++) cs += p[(size_t)k * E_];
    const int* dcol = dist + (size_t)b * E_ * E_ + j;
    int cnt = 0;
#pragma unroll 8
    for (int i = 0; i < E_; i++) cnt += (dcol[(size_t)i * E_] <= MAXN_) ? 1 : 0;
    ape[idx] = cs / (float)cnt;
}

// ---------------- launch ------------------------------------------------------
extern "C" void kernel_launch(void* const* d_in, const int* in_sizes, int n_in,
                              void* d_out, int out_size) {
    const float* x        = (const float*)d_in[0];
    const int*   dist     = (const int*)  d_in[1];
    const float* base_rpr = (const float*)d_in[2];
    const float* w_q      = (const float*)d_in[3];
    const float* w_k      = (const float*)d_in[4];
    const float* w_v      = (const float*)d_in[5];
    const float* w_fc     = (const float*)d_in[6];
    const float* ln_g     = (const float*)d_in[7];
    const float* ln_b     = (const float*)d_in[8];

    float* x_out = (float*)d_out;
    float* attn  = x_out + (size_t)B_ * DM_ * E_;
    float* ape   = attn  + (size_t)B_ * H_ * E_ * E_;

    float* ds;  cudaGetSymbolAddress((void**)&ds,  g_s);
    float* dqn; cudaGetSymbolAddress((void**)&dqn, g_qn);

    k_transpose<<<dim3(E_ / 32, DM_ / 32, B_), dim3(32, 8)>>>(x);
    k_layernorm<<<B_ * E_, 256>>>(ln_g, ln_b);

    k_qkv_mma<<<dim3(E_ / 128, 24, B_), 256>>>(dqn, ds, w_q, w_k, w_v);
    k_qr<<<B_ * H_ * E_ / 32, 256>>>(base_rpr);

    k_attn_fused<<<dim3(E_ / 64, B_ * H_), 256>>>(dist, attn);
    k_ogemm_mma<<<dim3(E_ / 128, 1, B_ * H_), 256>>>(attn);
    k_fc_mma<<<dim3(B_ * E_ / 128, DM_ / 64, 1), 256>>>(w_fc, x_out);
    k_ape_final<<<(B_ * E_) / 256, 256>>>(dist, ape);
}

// round 8
// speedup vs baseline: 1.6966x; 1.0019x over previous
#include <cuda_runtime.h>
#include <math.h>

#define B_  2
#define E_  1024
#define DM_ 512
#define H_  8
#define DK_ 64
#define DV_ 64
#define MAXN_ 5
#define NEGV (-1e9f)

__device__ __forceinline__ float tf32q(float x) {
    unsigned u;
    asm("cvt.rna.tf32.f32 %0, %1;" : "=r"(u) : "f"(x));
    return __uint_as_float(u);
}
__device__ __forceinline__ float4 tf32q4(float4 v) {
    v.x = tf32q(v.x); v.y = tf32q(v.y); v.z = tf32q(v.z); v.w = tf32q(v.w);
    return v;
}

#define MMA8(d, a, b)                                                        \
    asm volatile(                                                            \
        "mma.sync.aligned.m16n8k8.row.col.f32.tf32.tf32.f32 "                \
        "{%0,%1,%2,%3}, {%4,%5,%6,%7}, {%8,%9}, {%0,%1,%2,%3};\n"            \
        : "+f"((d)[0]), "+f"((d)[1]), "+f"((d)[2]), "+f"((d)[3])             \
        : "r"((a)[0]), "r"((a)[1]), "r"((a)[2]), "r"((a)[3]),                \
          "r"((b)[0]), "r"((b)[1]));

// ---------------- scratch ---------------------------------------------------
__device__ float g_s [B_*E_*DM_];
__device__ float g_qn[B_*E_*DM_];
__device__ float g_q [B_*H_*E_*DK_];
__device__ float g_k [B_*H_*E_*DK_];
__device__ float g_v [B_*H_*E_*DV_];
__device__ float g_o [B_*E_*H_*DV_];
__device__ float g_pcs2[B_*H_*32*E_];          // per (z, i-block) column sums
__device__ unsigned char g_d8[B_*E_*E_];       // packed clipped dist

// ---------------- 1. transpose x[b,d,e] -> s[b,e,d] ------------------------
__global__ void k_transpose(const float* __restrict__ x) {
    __shared__ float tile[32][33];
    int b = blockIdx.z;
    int e0 = blockIdx.x * 32;
    int d0 = blockIdx.y * 32;
    int tx = threadIdx.x, ty = threadIdx.y;
#pragma unroll
    for (int r = 0; r < 4; r++) {
        int d = d0 + ty + r * 8;
        tile[ty + r * 8][tx] = x[(size_t)b * DM_ * E_ + (size_t)d * E_ + e0 + tx];
    }
    __syncthreads();
#pragma unroll
    for (int r = 0; r < 4; r++) {
        int e = e0 + ty + r * 8;
        g_s[(size_t)b * E_ * DM_ + (size_t)e * DM_ + d0 + tx] = tile[tx][ty + r * 8];
    }
}

// ---------------- 2. LayerNorm ----------------------------------------------
__global__ void k_layernorm(const float* __restrict__ ln_g, const float* __restrict__ ln_b) {
    int row = blockIdx.x;
    const float* src = g_s + (size_t)row * DM_;
    int tid = threadIdx.x;
    float2 v = ((const float2*)src)[tid];
    float s1 = v.x + v.y;
    float s2 = v.x * v.x + v.y * v.y;
#pragma unroll
    for (int o = 16; o; o >>= 1) {
        s1 += __shfl_xor_sync(0xffffffff, s1, o);
        s2 += __shfl_xor_sync(0xffffffff, s2, o);
    }
    __shared__ float sh[16];
    __shared__ float s_mu, s_rstd;
    int w = tid >> 5, l = tid & 31;
    if (l == 0) { sh[w] = s1; sh[8 + w] = s2; }
    __syncthreads();
    if (tid == 0) {
        float a = 0.f, c = 0.f;
#pragma unroll
        for (int i = 0; i < 8; i++) { a += sh[i]; c += sh[8 + i]; }
        float mu  = a / (float)DM_;
        float var = c / (float)DM_ - mu * mu;
        s_mu = mu;
        s_rstd = 1.f / sqrtf(var + 1e-6f);
    }
    __syncthreads();
    float mu = s_mu, rstd = s_rstd;
    float2 gg = ((const float2*)ln_g)[tid];
    float2 bb = ((const float2*)ln_b)[tid];
    float2 o;
    o.x = (v.x - mu) * rstd * gg.x + bb.x;
    o.y = (v.y - mu) * rstd * gg.y + bb.y;
    ((float2*)(g_qn + (size_t)row * DM_))[tid] = o;
}

// ---------------- 3. fused QKV GEMM (tensor core) ---------------------------
__global__ __launch_bounds__(256) void k_qkv_mma(
    const float* __restrict__ A0, const float* __restrict__ A1,
    const float* __restrict__ Wq, const float* __restrict__ Wk,
    const float* __restrict__ Wv)
{
    __shared__ float As[128 * 36];
    __shared__ float Ws[32 * 72];
    int mat = blockIdx.y >> 3, h = blockIdx.y & 7, b = blockIdx.z;
    int m0 = blockIdx.x * 128;
    const float* A = (mat == 0) ? A0 : A1;
    const float* W = (mat == 0) ? Wq : (mat == 1 ? Wk : Wv);
    float* out = (mat == 0) ? g_q : (mat == 1 ? g_k : g_v);
    float scale = (mat == 0) ? 0.125f : 1.0f;

    int tid = threadIdx.x;
    int wid = tid >> 5, lane = tid & 31;
    int g = lane >> 2, t = lane & 3;
    int warpM = wid & 3, warpN = wid >> 2;

    const unsigned* Asu = (const unsigned*)As;
    const unsigned* Wsu = (const unsigned*)Ws;
    float acc[2][4][4] = {};
    size_t arow_base = ((size_t)b * E_ + m0);

    for (int k0 = 0; k0 < DM_; k0 += 32) {
        __syncthreads();
#pragma unroll
        for (int i = 0; i < 4; i++) {
            int f = tid + i * 256;
            int row = f >> 3, c4 = (f & 7) * 4;
            float4 v = tf32q4(*(const float4*)(A + (arow_base + row) * DM_ + k0 + c4));
            *(float4*)&As[row * 36 + c4] = v;
        }
#pragma unroll
        for (int i = 0; i < 2; i++) {
            int f = tid + i * 256;
            int row = f >> 4, c4 = (f & 15) * 4;
            float4 v = tf32q4(*(const float4*)(W + (size_t)(k0 + row) * (H_ * DK_) + h * 64 + c4));
            *(float4*)&Ws[row * 72 + c4] = v;
        }
        __syncthreads();
#pragma unroll
        for (int kk = 0; kk < 4; kk++) {
            int k = kk * 8;
            unsigned af[2][4], bf[4][2];
#pragma unroll
            for (int mb = 0; mb < 2; mb++) {
                int rb = warpM * 32 + mb * 16;
                af[mb][0] = Asu[(rb + g) * 36 + k + t];
                af[mb][1] = Asu[(rb + g + 8) * 36 + k + t];
                af[mb][2] = Asu[(rb + g) * 36 + k + t + 4];
                af[mb][3] = Asu[(rb + g + 8) * 36 + k + t + 4];
            }
#pragma unroll
            for (int nb = 0; nb < 4; nb++) {
                int cb = warpN * 32 + nb * 8 + g;
                bf[nb][0] = Wsu[(k + t) * 72 + cb];
                bf[nb][1] = Wsu[(k + t + 4) * 72 + cb];
            }
#pragma unroll
            for (int mb = 0; mb < 2; mb++)
#pragma unroll
                for (int nb = 0; nb < 4; nb++) MMA8(acc[mb][nb], af[mb], bf[nb])
        }
    }
    size_t obase = (((size_t)b * H_ + h) * E_ + m0) * 64;
#pragma unroll
    for (int mb = 0; mb < 2; mb++) {
        int r0 = warpM * 32 + mb * 16 + g;
#pragma unroll
        for (int nb = 0; nb < 4; nb++) {
            int c = warpN * 32 + nb * 8 + 2 * t;
            *(float2*)(out + obase + (size_t)r0 * 64 + c) =
                make_float2(acc[mb][nb][0] * scale, acc[mb][nb][1] * scale);
            *(float2*)(out + obase + (size_t)(r0 + 8) * 64 + c) =
                make_float2(acc[mb][nb][2] * scale, acc[mb][nb][3] * scale);
        }
    }
}

// ---------------- 4. pack dist -> int8 (clipped) -----------------------------
__global__ void k_pack(const int* __restrict__ dist) {
    int idx = blockIdx.x * 256 + threadIdx.x;      // over B*E*E/4
    int4 v = ((const int4*)dist)[idx];
    uchar4 o;
    o.x = (unsigned char)(v.x > 7 ? 7 : v.x);
    o.y = (unsigned char)(v.y > 7 ? 7 : v.y);
    o.z = (unsigned char)(v.z > 7 ? 7 : v.z);
    o.w = (unsigned char)(v.w > 7 ? 7 : v.w);
    ((uchar4*)g_d8)[idx] = o;
}

// ---------------- 5. flash attention: logits+softmax+attn-write+O+colsums ----
// grid (32, B*H): block owns 32 i-rows of one (b,h). 8 warps: 2(warpM) x 4(warpN).
__global__ __launch_bounds__(256) void k_flash(
    const float* __restrict__ base_rpr, float* __restrict__ attn)
{
    __shared__ float Qs[32 * 68];
    __shared__ float KP[64 * 68];      // K tile, reused as P tile in pass B
    __shared__ float Vs[64 * 72];
    __shared__ float rpr_s[384];
    __shared__ float qrs[32 * 6];
    __shared__ float rowm[32][4], rowl[32][4];
    __shared__ float mfin[32], linv[32];
    __shared__ float colpart[2][64];

    int iblk = blockIdx.x, i0 = iblk * 32;
    int z = blockIdx.y, b = z >> 3;
    int tid = threadIdx.x, wid = tid >> 5, lane = tid & 31;
    int g = lane >> 2, t = lane & 3;
    int warpM = wid & 1, warpN = wid >> 1;

    const unsigned* Qsu = (const unsigned*)Qs;
    const unsigned* KPu = (const unsigned*)KP;
    const unsigned* Vsu = (const unsigned*)Vs;

    // prologue: Q tile + rpr + qr table
    size_t qbase = ((size_t)z * E_ + i0) * 64;
#pragma unroll
    for (int i = 0; i < 2; i++) {
        int f = tid + i * 256;
        int row = f >> 4, c4 = (f & 15) * 4;
        float4 v = tf32q4(*(const float4*)(g_q + qbase + (size_t)row * 64 + c4));
        *(float4*)&Qs[row * 68 + c4] = v;
    }
    for (int tt = tid; tt < 384; tt += 256) rpr_s[tt] = tf32q(base_rpr[tt]);
    __syncthreads();
    if (tid < 192) {
        int row = tid / 6, c = tid % 6;
        float s = 0.f;
#pragma unroll 16
        for (int d = 0; d < 64; d++) s += Qs[row * 68 + d] * rpr_s[c * 64 + d];
        qrs[row * 6 + c] = s;
    }

    const unsigned char* dbase = g_d8 + (size_t)b * E_ * E_;
    int il0 = warpM * 16 + g, il1 = il0 + 8;
    int gi0 = i0 + il0, gi1 = i0 + il1;
    size_t kvbase = (size_t)z * E_ * 64;

    float m[2] = {-3.0e38f, -3.0e38f}, l[2] = {0.f, 0.f};

    // ---------------- pass A: online (m, l), registers only ----------------
    for (int jt = 0; jt < 16; jt++) {
        int j0 = jt * 64;
        __syncthreads();
#pragma unroll
        for (int i = 0; i < 4; i++) {
            int f = tid + i * 256;
            int row = f >> 4, c4 = (f & 15) * 4;
            float4 v = tf32q4(*(const float4*)(g_k + kvbase + (size_t)(j0 + row) * 64 + c4));
            *(float4*)&KP[row * 68 + c4] = v;
        }
        __syncthreads();
        float acc[2][4] = {};
#pragma unroll
        for (int kk = 0; kk < 8; kk++) {
            int k = kk * 8;
            unsigned af[4], bf[2][2];
            int rb = warpM * 16;
            af[0] = Qsu[(rb + g) * 68 + k + t];
            af[1] = Qsu[(rb + g + 8) * 68 + k + t];
            af[2] = Qsu[(rb + g) * 68 + k + t + 4];
            af[3] = Qsu[(rb + g + 8) * 68 + k + t + 4];
#pragma unroll
            for (int nb = 0; nb < 2; nb++) {
                int cb = warpN * 16 + nb * 8 + g;
                bf[nb][0] = KPu[cb * 68 + k + t];
                bf[nb][1] = KPu[cb * 68 + k + t + 4];
            }
#pragma unroll
            for (int nb = 0; nb < 2; nb++) MMA8(acc[nb], af, bf[nb])
        }
#pragma unroll
        for (int nb = 0; nb < 2; nb++) {
            int j = j0 + warpN * 16 + nb * 8 + 2 * t;
            uchar2 d0 = *(const uchar2*)(dbase + (size_t)gi0 * E_ + j);
            uchar2 d1 = *(const uchar2*)(dbase + (size_t)gi1 * E_ + j);
            float x00 = (d0.x <= MAXN_) ? acc[nb][0] + qrs[il0 * 6 + d0.x] : NEGV;
            float x01 = (d0.y <= MAXN_) ? acc[nb][1] + qrs[il0 * 6 + d0.y] : NEGV;
            float x10 = (d1.x <= MAXN_) ? acc[nb][2] + qrs[il1 * 6 + d1.x] : NEGV;
            float x11 = (d1.y <= MAXN_) ? acc[nb][3] + qrs[il1 * 6 + d1.y] : NEGV;
            float nm0 = fmaxf(m[0], fmaxf(x00, x01));
            l[0] = l[0] * __expf(m[0] - nm0) + __expf(x00 - nm0) + __expf(x01 - nm0);
            m[0] = nm0;
            float nm1 = fmaxf(m[1], fmaxf(x10, x11));
            l[1] = l[1] * __expf(m[1] - nm1) + __expf(x10 - nm1) + __expf(x11 - nm1);
            m[1] = nm1;
        }
    }
    // reduce (m,l) over t lanes, then over warpN via smem
#pragma unroll
    for (int r = 0; r < 2; r++)
#pragma unroll
        for (int off = 1; off < 4; off <<= 1) {
            float om = __shfl_xor_sync(0xffffffff, m[r], off);
            float ol = __shfl_xor_sync(0xffffffff, l[r], off);
            float nm = fmaxf(m[r], om);
            l[r] = l[r] * __expf(m[r] - nm) + ol * __expf(om - nm);
            m[r] = nm;
        }
    if (t == 0) {
        rowm[il0][warpN] = m[0]; rowl[il0][warpN] = l[0];
        rowm[il1][warpN] = m[1]; rowl[il1][warpN] = l[1];
    }
    __syncthreads();
    if (tid < 32) {
        float mm = rowm[tid][0], ll = rowl[tid][0];
#pragma unroll
        for (int w = 1; w < 4; w++) {
            float om = rowm[tid][w], ol = rowl[tid][w];
            float nm = fmaxf(mm, om);
            ll = ll * __expf(mm - nm) + ol * __expf(om - nm);
            mm = nm;
        }
        mfin[tid] = mm;
        linv[tid] = 1.f / ll;
    }

    // ---------------- pass B: recompute, normalize, write attn, O mma -------
    float* abase = attn + (size_t)z * E_ * E_;
    float oacc[2][4] = {};
    for (int jt = 0; jt < 16; jt++) {
        int j0 = jt * 64;
        __syncthreads();
#pragma unroll
        for (int i = 0; i < 4; i++) {
            int f = tid + i * 256;
            int row = f >> 4, c4 = (f & 15) * 4;
            float4 v = tf32q4(*(const float4*)(g_k + kvbase + (size_t)(j0 + row) * 64 + c4));
            *(float4*)&KP[row * 68 + c4] = v;
            float4 vv = tf32q4(*(const float4*)(g_v + kvbase + (size_t)(j0 + row) * 64 + c4));
            *(float4*)&Vs[row * 72 + c4] = vv;
        }
        __syncthreads();
        float acc[2][4] = {};
#pragma unroll
        for (int kk = 0; kk < 8; kk++) {
            int k = kk * 8;
            unsigned af[4], bf[2][2];
            int rb = warpM * 16;
            af[0] = Qsu[(rb + g) * 68 + k + t];
            af[1] = Qsu[(rb + g + 8) * 68 + k + t];
            af[2] = Qsu[(rb + g) * 68 + k + t + 4];
            af[3] = Qsu[(rb + g + 8) * 68 + k + t + 4];
#pragma unroll
            for (int nb = 0; nb < 2; nb++) {
                int cb = warpN * 16 + nb * 8 + g;
                bf[nb][0] = KPu[cb * 68 + k + t];
                bf[nb][1] = KPu[cb * 68 + k + t + 4];
            }
#pragma unroll
            for (int nb = 0; nb < 2; nb++) MMA8(acc[nb], af, bf[nb])
        }
        float p[2][4], colv[4];
        float m0v = mfin[il0], i0v = linv[il0];
        float m1v = mfin[il1], i1v = linv[il1];
#pragma unroll
        for (int nb = 0; nb < 2; nb++) {
            int j = j0 + warpN * 16 + nb * 8 + 2 * t;
            uchar2 d0 = *(const uchar2*)(dbase + (size_t)gi0 * E_ + j);
            uchar2 d1 = *(const uchar2*)(dbase + (size_t)gi1 * E_ + j);
            float x00 = (d0.x <= MAXN_) ? acc[nb][0] + qrs[il0 * 6 + d0.x] : NEGV;
            float x01 = (d0.y <= MAXN_) ? acc[nb][1] + qrs[il0 * 6 + d0.y] : NEGV;
            float x10 = (d1.x <= MAXN_) ? acc[nb][2] + qrs[il1 * 6 + d1.x] : NEGV;
            float x11 = (d1.y <= MAXN_) ? acc[nb][3] + qrs[il1 * 6 + d1.y] : NEGV;
            p[nb][0] = __expf(x00 - m0v) * i0v;
            p[nb][1] = __expf(x01 - m0v) * i0v;
            p[nb][2] = __expf(x10 - m1v) * i1v;
            p[nb][3] = __expf(x11 - m1v) * i1v;
            *(float2*)(abase + (size_t)gi0 * E_ + j) = make_float2(p[nb][0], p[nb][1]);
            *(float2*)(abase + (size_t)gi1 * E_ + j) = make_float2(p[nb][2], p[nb][3]);
            colv[nb * 2 + 0] = p[nb][0] + p[nb][2];
            colv[nb * 2 + 1] = p[nb][1] + p[nb][3];
        }
        __syncthreads();          // all warps done reading KP (K)
        // store tf32 P into KP rows 0..31
#pragma unroll
        for (int nb = 0; nb < 2; nb++) {
            int jl = warpN * 16 + nb * 8 + 2 * t;
            KP[il0 * 68 + jl]     = tf32q(p[nb][0]);
            KP[il0 * 68 + jl + 1] = tf32q(p[nb][1]);
            KP[il1 * 68 + jl]     = tf32q(p[nb][2]);
            KP[il1 * 68 + jl + 1] = tf32q(p[nb][3]);
        }
        __syncthreads();          // P ready
        // O += P(32xj64) @ V(j64 x dv64)
#pragma unroll
        for (int kk = 0; kk < 8; kk++) {
            int k = kk * 8;
            unsigned af[4], bf[2][2];
            int rb = warpM * 16;
            af[0] = KPu[(rb + g) * 68 + k + t];
            af[1] = KPu[(rb + g + 8) * 68 + k + t];
            af[2] = KPu[(rb + g) * 68 + k + t + 4];
            af[3] = KPu[(rb + g + 8) * 68 + k + t + 4];
#pragma unroll
            for (int nb = 0; nb < 2; nb++) {
                int cb = warpN * 16 + nb * 8 + g;
                bf[nb][0] = Vsu[(k + t) * 72 + cb];
                bf[nb][1] = Vsu[(k + t + 4) * 72 + cb];
            }
#pragma unroll
            for (int nb = 0; nb < 2; nb++) MMA8(oacc[nb], af, bf[nb])
        }
        // column sums: reduce over g lanes (offsets 4,8,16)
#pragma unroll
        for (int i = 0; i < 4; i++) {
            colv[i] += __shfl_xor_sync(0xffffffff, colv[i], 4);
            colv[i] += __shfl_xor_sync(0xffffffff, colv[i], 8);
            colv[i] += __shfl_xor_sync(0xffffffff, colv[i], 16);
        }
        if (lane < 4) {           // g == 0, lane == t
            int cb = warpN * 16 + 2 * t;
            colpart[warpM][cb + 0] = colv[0];
            colpart[warpM][cb + 1] = colv[1];
            colpart[warpM][cb + 8] = colv[2];
            colpart[warpM][cb + 9] = colv[3];
        }
        __syncthreads();
        if (tid < 64)
            g_pcs2[((size_t)z * 32 + iblk) * E_ + j0 + tid] =
                colpart[0][tid] + colpart[1][tid];
    }
    // write O tile: g_o[(b*E + i)*512 + h*64 + dv]
    int h = z & 7;
#pragma unroll
    for (int nb = 0; nb < 2; nb++) {
        int dv = h * 64 + warpN * 16 + nb * 8 + 2 * t;
        *(float2*)(g_o + ((size_t)b * E_ + gi0) * 512 + dv) =
            make_float2(oacc[nb][0], oacc[nb][1]);
        *(float2*)(g_o + ((size_t)b * E_ + gi1) * 512 + dv) =
            make_float2(oacc[nb][2], oacc[nb][3]);
    }
}

// ---------------- 6. FC + residual + transposed store (tensor core) ----------
__global__ __launch_bounds__(256) void k_fc_mma(
    const float* __restrict__ w_fc, float* __restrict__ xout)
{
    __shared__ float sm[64 * 132];
    float* As = sm;
    float* Ws = sm + 128 * 36;
    int m0 = blockIdx.x * 128, n0 = blockIdx.y * 64;
    int b = m0 >> 10, e0 = m0 & 1023;
    int tid = threadIdx.x;
    int wid = tid >> 5, lane = tid & 31;
    int g = lane >> 2, t = lane & 3;
    int warpM = wid & 3, warpN = wid >> 2;

    const unsigned* Asu = (const unsigned*)As;
    const unsigned* Wsu = (const unsigned*)Ws;
    float acc[2][4][4] = {};

    for (int k0 = 0; k0 < 512; k0 += 32) {
        __syncthreads();
#pragma unroll
        for (int i = 0; i < 4; i++) {
            int f = tid + i * 256;
            int row = f >> 3, c4 = (f & 7) * 4;
            float4 v = tf32q4(*(const float4*)(g_o + (size_t)(m0 + row) * 512 + k0 + c4));
            *(float4*)&As[row * 36 + c4] = v;
        }
#pragma unroll
        for (int i = 0; i < 2; i++) {
            int f = tid + i * 256;
            int row = f >> 4, c4 = (f & 15) * 4;
            float4 v = tf32q4(*(const float4*)(w_fc + (size_t)(k0 + row) * DM_ + n0 + c4));
            *(float4*)&Ws[row * 72 + c4] = v;
        }
        __syncthreads();
#pragma unroll
        for (int kk = 0; kk < 4; kk++) {
            int k = kk * 8;
            unsigned af[2][4], bf[4][2];
#pragma unroll
            for (int mb = 0; mb < 2; mb++) {
                int rb = warpM * 32 + mb * 16;
                af[mb][0] = Asu[(rb + g) * 36 + k + t];
                af[mb][1] = Asu[(rb + g + 8) * 36 + k + t];
                af[mb][2] = Asu[(rb + g) * 36 + k + t + 4];
                af[mb][3] = Asu[(rb + g + 8) * 36 + k + t + 4];
            }
#pragma unroll
            for (int nb = 0; nb < 4; nb++) {
                int cb = warpN * 32 + nb * 8 + g;
                bf[nb][0] = Wsu[(k + t) * 72 + cb];
                bf[nb][1] = Wsu[(k + t + 4) * 72 + cb];
            }
#pragma unroll
            for (int mb = 0; mb < 2; mb++)
#pragma unroll
                for (int nb = 0; nb < 4; nb++) MMA8(acc[mb][nb], af[mb], bf[nb])
        }
    }
    __syncthreads();
#pragma unroll
    for (int mb = 0; mb < 2; mb++) {
        int el0 = warpM * 32 + mb * 16 + g;
#pragma unroll
        for (int nb = 0; nb < 4; nb++) {
            int nl = warpN * 32 + nb * 8 + 2 * t;
#pragma unroll
            for (int half = 0; half < 2; half++) {
                int el = el0 + half * 8;
                const float* res = g_s + (size_t)(m0 + el) * DM_ + n0 + nl;
                sm[(nl + 0) * 132 + el] = acc[mb][nb][half * 2 + 0] + res[0];
                sm[(nl + 1) * 132 + el] = acc[mb][nb][half * 2 + 1] + res[1];
            }
        }
    }
    __syncthreads();
#pragma unroll
    for (int i = 0; i < 8; i++) {
        int f = tid + i * 256;
        int row = f >> 5, c4 = (f & 31) * 4;
        float4 v = *(const float4*)&sm[row * 132 + c4];
        *(float4*)(xout + ((size_t)b * DM_ + n0 + row) * E_ + e0 + c4) = v;
    }
}

// ---------------- 7. ape final -------------------------------------------------
__global__ void k_ape_final(float* __restrict__ ape) {
    int idx = blockIdx.x * 256 + threadIdx.x;   // 0 .. B*E-1
    int b = idx >> 10, j = idx & (E_ - 1);
    float cs = 0.f;
    const float* p = g_pcs2 + (size_t)b * 8 * 32 * E_ + j;
#pragma unroll 8
    for (int k = 0; k < 256; k++) cs += p[(size_t)k * E_];
    const unsigned char* dcol = g_d8 + (size_t)b * E_ * E_ + j;
    int cnt = 0;
#pragma unroll 8
    for (int i = 0; i < E_; i++) cnt += (dcol[(size_t)i * E_] <= MAXN_) ? 1 : 0;
    ape[idx] = cs / (float)cnt;
}

// ---------------- launch ------------------------------------------------------
extern "C" void kernel_launch(void* const* d_in, const int* in_sizes, int n_in,
                              void* d_out, int out_size) {
    const float* x        = (const float*)d_in[0];
    const int*   dist     = (const int*)  d_in[1];
    const float* base_rpr = (const float*)d_in[2];
    const float* w_q      = (const float*)d_in[3];
    const float* w_k      = (const float*)d_in[4];
    const float* w_v      = (const float*)d_in[5];
    const float* w_fc     = (const float*)d_in[6];
    const float* ln_g     = (const float*)d_in[7];
    const float* ln_b     = (const float*)d_in[8];

    float* x_out = (float*)d_out;
    float* attn  = x_out + (size_t)B_ * DM_ * E_;
    float* ape   = attn  + (size_t)B_ * H_ * E_ * E_;

    float* ds;  cudaGetSymbolAddress((void**)&ds,  g_s);
    float* dqn; cudaGetSymbolAddress((void**)&dqn, g_qn);

    k_transpose<<<dim3(E_ / 32, DM_ / 32, B_), dim3(32, 8)>>>(x);
    k_layernorm<<<B_ * E_, 256>>>(ln_g, ln_b);
    k_pack<<<(B_ * E_ * E_) / 1024, 256>>>(dist);

    k_qkv_mma<<<dim3(E_ / 128, 24, B_), 256>>>(dqn, ds, w_q, w_k, w_v);

    k_flash<<<dim3(32, B_ * H_), 256>>>(base_rpr, attn);
    k_fc_mma<<<dim3(B_ * E_ / 128, DM_ / 64, 1), 256>>>(w_fc, x_out);
    k_ape_final<<<(B_ * E_) / 256, 256>>>(ape);
}

// round 9
// speedup vs baseline: 1.7817x; 1.0502x over previous
#include <cuda_runtime.h>
#include <math.h>

#define B_  2
#define E_  1024
#define DM_ 512
#define H_  8
#define DK_ 64
#define DV_ 64
#define MAXN_ 5
#define NEGV (-1e9f)

__device__ __forceinline__ float tf32q(float x) {
    unsigned u;
    asm("cvt.rna.tf32.f32 %0, %1;" : "=r"(u) : "f"(x));
    return __uint_as_float(u);
}
__device__ __forceinline__ float4 tf32q4(float4 v) {
    v.x = tf32q(v.x); v.y = tf32q(v.y); v.z = tf32q(v.z); v.w = tf32q(v.w);
    return v;
}

#define MMA8(d, a, b)                                                        \
    asm volatile(                                                            \
        "mma.sync.aligned.m16n8k8.row.col.f32.tf32.tf32.f32 "                \
        "{%0,%1,%2,%3}, {%4,%5,%6,%7}, {%8,%9}, {%0,%1,%2,%3};\n"            \
        : "+f"((d)[0]), "+f"((d)[1]), "+f"((d)[2]), "+f"((d)[3])             \
        : "r"((a)[0]), "r"((a)[1]), "r"((a)[2]), "r"((a)[3]),                \
          "r"((b)[0]), "r"((b)[1]));

// ---------------- scratch ---------------------------------------------------
__device__ float g_s [B_*E_*DM_];
__device__ float g_qn[B_*E_*DM_];
__device__ float g_q [B_*H_*E_*DK_];
__device__ float g_k [B_*H_*E_*DK_];
__device__ float g_v [B_*H_*E_*DV_];
__device__ float g_o [B_*E_*H_*DV_];
__device__ float g_pcs2[B_*H_*16*E_];          // per (z, 64-row block) col sums
__device__ float g_mused[B_*H_*E_*16];         // per-row per-tile max used
__device__ float g_mfin [B_*H_*E_];
__device__ float g_linv [B_*H_*E_];
__device__ unsigned char g_d8[B_*E_*E_];       // packed clipped dist

// ---------------- 1. transpose x[b,d,e] -> s[b,e,d] ------------------------
__global__ void k_transpose(const float* __restrict__ x) {
    __shared__ float tile[32][33];
    int b = blockIdx.z;
    int e0 = blockIdx.x * 32;
    int d0 = blockIdx.y * 32;
    int tx = threadIdx.x, ty = threadIdx.y;
#pragma unroll
    for (int r = 0; r < 4; r++) {
        int d = d0 + ty + r * 8;
        tile[ty + r * 8][tx] = x[(size_t)b * DM_ * E_ + (size_t)d * E_ + e0 + tx];
    }
    __syncthreads();
#pragma unroll
    for (int r = 0; r < 4; r++) {
        int e = e0 + ty + r * 8;
        g_s[(size_t)b * E_ * DM_ + (size_t)e * DM_ + d0 + tx] = tile[tx][ty + r * 8];
    }
}

// ---------------- 2. LayerNorm ----------------------------------------------
__global__ void k_layernorm(const float* __restrict__ ln_g, const float* __restrict__ ln_b) {
    int row = blockIdx.x;
    const float* src = g_s + (size_t)row * DM_;
    int tid = threadIdx.x;
    float2 v = ((const float2*)src)[tid];
    float s1 = v.x + v.y;
    float s2 = v.x * v.x + v.y * v.y;
#pragma unroll
    for (int o = 16; o; o >>= 1) {
        s1 += __shfl_xor_sync(0xffffffff, s1, o);
        s2 += __shfl_xor_sync(0xffffffff, s2, o);
    }
    __shared__ float sh[16];
    __shared__ float s_mu, s_rstd;
    int w = tid >> 5, l = tid & 31;
    if (l == 0) { sh[w] = s1; sh[8 + w] = s2; }
    __syncthreads();
    if (tid == 0) {
        float a = 0.f, c = 0.f;
#pragma unroll
        for (int i = 0; i < 8; i++) { a += sh[i]; c += sh[8 + i]; }
        float mu  = a / (float)DM_;
        float var = c / (float)DM_ - mu * mu;
        s_mu = mu;
        s_rstd = 1.f / sqrtf(var + 1e-6f);
    }
    __syncthreads();
    float mu = s_mu, rstd = s_rstd;
    float2 gg = ((const float2*)ln_g)[tid];
    float2 bb = ((const float2*)ln_b)[tid];
    float2 o;
    o.x = (v.x - mu) * rstd * gg.x + bb.x;
    o.y = (v.y - mu) * rstd * gg.y + bb.y;
    ((float2*)(g_qn + (size_t)row * DM_))[tid] = o;
}

// ---------------- 3. fused QKV GEMM (tensor core) ---------------------------
__global__ __launch_bounds__(256) void k_qkv_mma(
    const float* __restrict__ A0, const float* __restrict__ A1,
    const float* __restrict__ Wq, const float* __restrict__ Wk,
    const float* __restrict__ Wv)
{
    __shared__ float As[128 * 36];
    __shared__ float Ws[32 * 72];
    int mat = blockIdx.y >> 3, h = blockIdx.y & 7, b = blockIdx.z;
    int m0 = blockIdx.x * 128;
    const float* A = (mat == 0) ? A0 : A1;
    const float* W = (mat == 0) ? Wq : (mat == 1 ? Wk : Wv);
    float* out = (mat == 0) ? g_q : (mat == 1 ? g_k : g_v);
    float scale = (mat == 0) ? 0.125f : 1.0f;

    int tid = threadIdx.x;
    int wid = tid >> 5, lane = tid & 31;
    int g = lane >> 2, t = lane & 3;
    int warpM = wid & 3, warpN = wid >> 2;

    const unsigned* Asu = (const unsigned*)As;
    const unsigned* Wsu = (const unsigned*)Ws;
    float acc[2][4][4] = {};
    size_t arow_base = ((size_t)b * E_ + m0);

    for (int k0 = 0; k0 < DM_; k0 += 32) {
        __syncthreads();
#pragma unroll
        for (int i = 0; i < 4; i++) {
            int f = tid + i * 256;
            int row = f >> 3, c4 = (f & 7) * 4;
            float4 v = tf32q4(*(const float4*)(A + (arow_base + row) * DM_ + k0 + c4));
            *(float4*)&As[row * 36 + c4] = v;
        }
#pragma unroll
        for (int i = 0; i < 2; i++) {
            int f = tid + i * 256;
            int row = f >> 4, c4 = (f & 15) * 4;
            float4 v = tf32q4(*(const float4*)(W + (size_t)(k0 + row) * (H_ * DK_) + h * 64 + c4));
            *(float4*)&Ws[row * 72 + c4] = v;
        }
        __syncthreads();
#pragma unroll
        for (int kk = 0; kk < 4; kk++) {
            int k = kk * 8;
            unsigned af[2][4], bf[4][2];
#pragma unroll
            for (int mb = 0; mb < 2; mb++) {
                int rb = warpM * 32 + mb * 16;
                af[mb][0] = Asu[(rb + g) * 36 + k + t];
                af[mb][1] = Asu[(rb + g + 8) * 36 + k + t];
                af[mb][2] = Asu[(rb + g) * 36 + k + t + 4];
                af[mb][3] = Asu[(rb + g + 8) * 36 + k + t + 4];
            }
#pragma unroll
            for (int nb = 0; nb < 4; nb++) {
                int cb = warpN * 32 + nb * 8 + g;
                bf[nb][0] = Wsu[(k + t) * 72 + cb];
                bf[nb][1] = Wsu[(k + t + 4) * 72 + cb];
            }
#pragma unroll
            for (int mb = 0; mb < 2; mb++)
#pragma unroll
                for (int nb = 0; nb < 4; nb++) MMA8(acc[mb][nb], af[mb], bf[nb])
        }
    }
    size_t obase = (((size_t)b * H_ + h) * E_ + m0) * 64;
#pragma unroll
    for (int mb = 0; mb < 2; mb++) {
        int r0 = warpM * 32 + mb * 16 + g;
#pragma unroll
        for (int nb = 0; nb < 4; nb++) {
            int c = warpN * 32 + nb * 8 + 2 * t;
            *(float2*)(out + obase + (size_t)r0 * 64 + c) =
                make_float2(acc[mb][nb][0] * scale, acc[mb][nb][1] * scale);
            *(float2*)(out + obase + (size_t)(r0 + 8) * 64 + c) =
                make_float2(acc[mb][nb][2] * scale, acc[mb][nb][3] * scale);
        }
    }
}

// ---------------- 4. pack dist -> int8 (clipped) -----------------------------
__global__ void k_pack(const int* __restrict__ dist) {
    int idx = blockIdx.x * 256 + threadIdx.x;
    int4 v = ((const int4*)dist)[idx];
    uchar4 o;
    o.x = (unsigned char)(v.x > 7 ? 7 : v.x);
    o.y = (unsigned char)(v.y > 7 ? 7 : v.y);
    o.z = (unsigned char)(v.z > 7 ? 7 : v.z);
    o.w = (unsigned char)(v.w > 7 ? 7 : v.w);
    ((uchar4*)g_d8)[idx] = o;
}

// ---------------- 5. single-pass flash: QK+softmax(online)+p-write+O ----------
// grid (32, B*H): block owns 32 i-rows. 8 warps: 2(warpM rows) x 4(warpN cols).
__global__ __launch_bounds__(256) void k_flash(
    const float* __restrict__ base_rpr, float* __restrict__ attn)
{
    __shared__ float Qs[32 * 68];
    __shared__ float KP[64 * 68];      // K tile; rows 0..31 reused as P
    __shared__ float Vs[64 * 72];
    __shared__ float rpr_s[384];
    __shared__ float qrs[32 * 6];
    __shared__ float rowm[32][4];
    __shared__ float rowl[32][4];
    __shared__ float linv_s[32];

    int iblk = blockIdx.x, i0 = iblk * 32;
    int z = blockIdx.y, b = z >> 3;
    int tid = threadIdx.x, wid = tid >> 5, lane = tid & 31;
    int g = lane >> 2, t = lane & 3;
    int warpM = wid & 1, warpN = wid >> 1;

    const unsigned* Qsu = (const unsigned*)Qs;
    const unsigned* KPu = (const unsigned*)KP;
    const unsigned* Vsu = (const unsigned*)Vs;

    // prologue: Q tile + rpr + qr table
    size_t qbase = ((size_t)z * E_ + i0) * 64;
#pragma unroll
    for (int i = 0; i < 2; i++) {
        int f = tid + i * 256;
        int row = f >> 4, c4 = (f & 15) * 4;
        float4 v = tf32q4(*(const float4*)(g_q + qbase + (size_t)row * 64 + c4));
        *(float4*)&Qs[row * 68 + c4] = v;
    }
    for (int tt = tid; tt < 384; tt += 256) rpr_s[tt] = tf32q(base_rpr[tt]);
    __syncthreads();
    if (tid < 192) {
        int row = tid / 6, c = tid % 6;
        float s = 0.f;
#pragma unroll 16
        for (int d = 0; d < 64; d++) s += Qs[row * 68 + d] * rpr_s[c * 64 + d];
        qrs[row * 6 + c] = s;
    }

    const unsigned char* dbase = g_d8 + (size_t)b * E_ * E_;
    int il0 = warpM * 16 + g, il1 = il0 + 8;
    int gi0 = i0 + il0, gi1 = i0 + il1;
    size_t kvbase = (size_t)z * E_ * 64;
    float* abase = attn + (size_t)z * E_ * E_;

    float m[2] = {-3.0e38f, -3.0e38f}, l[2] = {0.f, 0.f};
    float oacc[2][4] = {};

    for (int jt = 0; jt < 16; jt++) {
        int j0 = jt * 64;
        __syncthreads();                         // KP/Vs free (prev PV mma done)
#pragma unroll
        for (int i = 0; i < 4; i++) {
            int f = tid + i * 256;
            int row = f >> 4, c4 = (f & 15) * 4;
            float4 v = tf32q4(*(const float4*)(g_k + kvbase + (size_t)(j0 + row) * 64 + c4));
            *(float4*)&KP[row * 68 + c4] = v;
            float4 vv = tf32q4(*(const float4*)(g_v + kvbase + (size_t)(j0 + row) * 64 + c4));
            *(float4*)&Vs[row * 72 + c4] = vv;
        }
        __syncthreads();
        // QK mma
        float acc[2][4] = {};
#pragma unroll
        for (int kk = 0; kk < 8; kk++) {
            int k = kk * 8;
            unsigned af[4], bf[2][2];
            int rb = warpM * 16;
            af[0] = Qsu[(rb + g) * 68 + k + t];
            af[1] = Qsu[(rb + g + 8) * 68 + k + t];
            af[2] = Qsu[(rb + g) * 68 + k + t + 4];
            af[3] = Qsu[(rb + g + 8) * 68 + k + t + 4];
#pragma unroll
            for (int nb = 0; nb < 2; nb++) {
                int cb = warpN * 16 + nb * 8 + g;
                bf[nb][0] = KPu[cb * 68 + k + t];
                bf[nb][1] = KPu[cb * 68 + k + t + 4];
            }
#pragma unroll
            for (int nb = 0; nb < 2; nb++) MMA8(acc[nb], af, bf[nb])
        }
        // epilogue: x = acc + qr[dist] (masked); tile row max
        float xv[2][4];
        float tm0 = -3.0e38f, tm1 = -3.0e38f;
#pragma unroll
        for (int nb = 0; nb < 2; nb++) {
            int j = j0 + warpN * 16 + nb * 8 + 2 * t;
            uchar2 d0 = *(const uchar2*)(dbase + (size_t)gi0 * E_ + j);
            uchar2 d1 = *(const uchar2*)(dbase + (size_t)gi1 * E_ + j);
            xv[nb][0] = (d0.x <= MAXN_) ? acc[nb][0] + qrs[il0 * 6 + d0.x] : NEGV;
            xv[nb][1] = (d0.y <= MAXN_) ? acc[nb][1] + qrs[il0 * 6 + d0.y] : NEGV;
            xv[nb][2] = (d1.x <= MAXN_) ? acc[nb][2] + qrs[il1 * 6 + d1.x] : NEGV;
            xv[nb][3] = (d1.y <= MAXN_) ? acc[nb][3] + qrs[il1 * 6 + d1.y] : NEGV;
            tm0 = fmaxf(tm0, fmaxf(xv[nb][0], xv[nb][1]));
            tm1 = fmaxf(tm1, fmaxf(xv[nb][2], xv[nb][3]));
        }
#pragma unroll
        for (int off = 1; off < 4; off <<= 1) {
            tm0 = fmaxf(tm0, __shfl_xor_sync(0xffffffff, tm0, off));
            tm1 = fmaxf(tm1, __shfl_xor_sync(0xffffffff, tm1, off));
        }
        if (t == 0) { rowm[il0][warpN] = tm0; rowm[il1][warpN] = tm1; }
        __syncthreads();                          // also: all QK mma reads of KP done
        float nm0 = fmaxf(fmaxf(rowm[il0][0], rowm[il0][1]),
                          fmaxf(rowm[il0][2], rowm[il0][3]));
        float nm1 = fmaxf(fmaxf(rowm[il1][0], rowm[il1][1]),
                          fmaxf(rowm[il1][2], rowm[il1][3]));
        nm0 = fmaxf(m[0], nm0);
        nm1 = fmaxf(m[1], nm1);
        float sc0 = __expf(m[0] - nm0), sc1 = __expf(m[1] - nm1);
        m[0] = nm0; m[1] = nm1;
        l[0] *= sc0; l[1] *= sc1;
#pragma unroll
        for (int nb = 0; nb < 2; nb++) {
            oacc[nb][0] *= sc0; oacc[nb][1] *= sc0;
            oacc[nb][2] *= sc1; oacc[nb][3] *= sc1;
        }
        // p = exp(x - m); write unnormalized p to attn; stage tf32 P in KP
#pragma unroll
        for (int nb = 0; nb < 2; nb++) {
            int jl = warpN * 16 + nb * 8 + 2 * t;
            int j = j0 + jl;
            float p00 = __expf(xv[nb][0] - nm0);
            float p01 = __expf(xv[nb][1] - nm0);
            float p10 = __expf(xv[nb][2] - nm1);
            float p11 = __expf(xv[nb][3] - nm1);
            l[0] += p00 + p01;
            l[1] += p10 + p11;
            *(float2*)(abase + (size_t)gi0 * E_ + j) = make_float2(p00, p01);
            *(float2*)(abase + (size_t)gi1 * E_ + j) = make_float2(p10, p11);
            KP[il0 * 68 + jl]     = tf32q(p00);
            KP[il0 * 68 + jl + 1] = tf32q(p01);
            KP[il1 * 68 + jl]     = tf32q(p10);
            KP[il1 * 68 + jl + 1] = tf32q(p11);
        }
        if (warpN == 0 && t == 0) {
            g_mused[((size_t)z * E_ + gi0) * 16 + jt] = nm0;
            g_mused[((size_t)z * E_ + gi1) * 16 + jt] = nm1;
        }
        __syncthreads();                          // P tile ready
        // O += P(32 x 64) @ V(64 x 64)
#pragma unroll
        for (int kk = 0; kk < 8; kk++) {
            int k = kk * 8;
            unsigned af[4], bf[2][2];
            int rb = warpM * 16;
            af[0] = KPu[(rb + g) * 68 + k + t];
            af[1] = KPu[(rb + g + 8) * 68 + k + t];
            af[2] = KPu[(rb + g) * 68 + k + t + 4];
            af[3] = KPu[(rb + g + 8) * 68 + k + t + 4];
#pragma unroll
            for (int nb = 0; nb < 2; nb++) {
                int cb = warpN * 16 + nb * 8 + g;
                bf[nb][0] = Vsu[(k + t) * 72 + cb];
                bf[nb][1] = Vsu[(k + t + 4) * 72 + cb];
            }
#pragma unroll
            for (int nb = 0; nb < 2; nb++) MMA8(oacc[nb], af, bf[nb])
        }
    }
    // reduce l over t lanes, then warps; publish m_final, 1/l
#pragma unroll
    for (int off = 1; off < 4; off <<= 1) {
        l[0] += __shfl_xor_sync(0xffffffff, l[0], off);
        l[1] += __shfl_xor_sync(0xffffffff, l[1], off);
    }
    if (t == 0) { rowl[il0][warpN] = l[0]; rowl[il1][warpN] = l[1]; }
    __syncthreads();
    if (tid < 32) {
        float ll = rowl[tid][0] + rowl[tid][1] + rowl[tid][2] + rowl[tid][3];
        linv_s[tid] = 1.f / ll;
    }
    __syncthreads();
    float inv0 = linv_s[il0], inv1 = linv_s[il1];
    if (warpN == 0 && t == 0) {
        g_mfin[(size_t)z * E_ + gi0] = m[0];
        g_mfin[(size_t)z * E_ + gi1] = m[1];
        g_linv[(size_t)z * E_ + gi0] = inv0;
        g_linv[(size_t)z * E_ + gi1] = inv1;
    }
    // write O: g_o[(b*E + i)*512 + h*64 + dv]
    int h = z & 7;
#pragma unroll
    for (int nb = 0; nb < 2; nb++) {
        int dv = h * 64 + warpN * 16 + nb * 8 + 2 * t;
        *(float2*)(g_o + ((size_t)b * E_ + gi0) * 512 + dv) =
            make_float2(oacc[nb][0] * inv0, oacc[nb][1] * inv0);
        *(float2*)(g_o + ((size_t)b * E_ + gi1) * 512 + dv) =
            make_float2(oacc[nb][2] * inv1, oacc[nb][3] * inv1);
    }
}

// ---------------- 6. fixup: rescale attn to final values + col partials -------
// grid B*H*16, block 256: 64 rows x 1024 cols each
__global__ void k_fixup(float* __restrict__ attn) {
    __shared__ float f[64 * 16];
    int bid = blockIdx.x;
    int z = bid >> 4, iblk = bid & 15;
    int i0 = iblk * 64;
    int tid = threadIdx.x;
#pragma unroll
    for (int k = 0; k < 4; k++) {
        int idx = tid + k * 256;
        int row = idx >> 4, tile = idx & 15;
        size_t gi = (size_t)z * E_ + i0 + row;
        f[idx] = __expf(g_mused[gi * 16 + tile] - g_mfin[gi]) * g_linv[gi];
    }
    __syncthreads();
    int j = tid * 4;
    int tile = tid >> 4;
    float4 cs = make_float4(0.f, 0.f, 0.f, 0.f);
    float* arow = attn + ((size_t)z * E_ + i0) * E_ + j;
#pragma unroll 4
    for (int r = 0; r < 64; r++) {
        float4 x = *(float4*)(arow + (size_t)r * E_);
        float fac = f[r * 16 + tile];
        x.x *= fac; x.y *= fac; x.z *= fac; x.w *= fac;
        *(float4*)(arow + (size_t)r * E_) = x;
        cs.x += x.x; cs.y += x.y; cs.z += x.z; cs.w += x.w;
    }
    *(float4*)(g_pcs2 + ((size_t)z * 16 + iblk) * E_ + j) = cs;
}

// ---------------- 7. FC + residual + transposed store (tensor core) ----------
__global__ __launch_bounds__(256) void k_fc_mma(
    const float* __restrict__ w_fc, float* __restrict__ xout)
{
    __shared__ float sm[64 * 132];
    float* As = sm;
    float* Ws = sm + 128 * 36;
    int m0 = blockIdx.x * 128, n0 = blockIdx.y * 64;
    int b = m0 >> 10, e0 = m0 & 1023;
    int tid = threadIdx.x;
    int wid = tid >> 5, lane = tid & 31;
    int g = lane >> 2, t = lane & 3;
    int warpM = wid & 3, warpN = wid >> 2;

    const unsigned* Asu = (const unsigned*)As;
    const unsigned* Wsu = (const unsigned*)Ws;
    float acc[2][4][4] = {};

    for (int k0 = 0; k0 < 512; k0 += 32) {
        __syncthreads();
#pragma unroll
        for (int i = 0; i < 4; i++) {
            int f = tid + i * 256;
            int row = f >> 3, c4 = (f & 7) * 4;
            float4 v = tf32q4(*(const float4*)(g_o + (size_t)(m0 + row) * 512 + k0 + c4));
            *(float4*)&As[row * 36 + c4] = v;
        }
#pragma unroll
        for (int i = 0; i < 2; i++) {
            int f = tid + i * 256;
            int row = f >> 4, c4 = (f & 15) * 4;
            float4 v = tf32q4(*(const float4*)(w_fc + (size_t)(k0 + row) * DM_ + n0 + c4));
            *(float4*)&Ws[row * 72 + c4] = v;
        }
        __syncthreads();
#pragma unroll
        for (int kk = 0; kk < 4; kk++) {
            int k = kk * 8;
            unsigned af[2][4], bf[4][2];
#pragma unroll
            for (int mb = 0; mb < 2; mb++) {
                int rb = warpM * 32 + mb * 16;
                af[mb][0] = Asu[(rb + g) * 36 + k + t];
                af[mb][1] = Asu[(rb + g + 8) * 36 + k + t];
                af[mb][2] = Asu[(rb + g) * 36 + k + t + 4];
                af[mb][3] = Asu[(rb + g + 8) * 36 + k + t + 4];
            }
#pragma unroll
            for (int nb = 0; nb < 4; nb++) {
                int cb = warpN * 32 + nb * 8 + g;
                bf[nb][0] = Wsu[(k + t) * 72 + cb];
                bf[nb][1] = Wsu[(k + t + 4) * 72 + cb];
            }
#pragma unroll
            for (int mb = 0; mb < 2; mb++)
#pragma unroll
                for (int nb = 0; nb < 4; nb++) MMA8(acc[mb][nb], af[mb], bf[nb])
        }
    }
    __syncthreads();
#pragma unroll
    for (int mb = 0; mb < 2; mb++) {
        int el0 = warpM * 32 + mb * 16 + g;
#pragma unroll
        for (int nb = 0; nb < 4; nb++) {
            int nl = warpN * 32 + nb * 8 + 2 * t;
#pragma unroll
            for (int half = 0; half < 2; half++) {
                int el = el0 + half * 8;
                const float* res = g_s + (size_t)(m0 + el) * DM_ + n0 + nl;
                sm[(nl + 0) * 132 + el] = acc[mb][nb][half * 2 + 0] + res[0];
                sm[(nl + 1) * 132 + el] = acc[mb][nb][half * 2 + 1] + res[1];
            }
        }
    }
    __syncthreads();
#pragma unroll
    for (int i = 0; i < 8; i++) {
        int f = tid + i * 256;
        int row = f >> 5, c4 = (f & 31) * 4;
        float4 v = *(const float4*)&sm[row * 132 + c4];
        *(float4*)(xout + ((size_t)b * DM_ + n0 + row) * E_ + e0 + c4) = v;
    }
}

// ---------------- 8. ape final -------------------------------------------------
__global__ void k_ape_final(float* __restrict__ ape) {
    int idx = blockIdx.x * 256 + threadIdx.x;   // 0 .. B*E-1
    int b = idx >> 10, j = idx & (E_ - 1);
    float cs = 0.f;
    const float* p = g_pcs2 + (size_t)b * 8 * 16 * E_ + j;
#pragma unroll 8
    for (int k = 0; k < 128; k++) cs += p[(size_t)k * E_];
    const unsigned char* dcol = g_d8 + (size_t)b * E_ * E_ + j;
    int cnt = 0;
#pragma unroll 8
    for (int i = 0; i < E_; i++) cnt += (dcol[(size_t)i * E_] <= MAXN_) ? 1 : 0;
    ape[idx] = cs / (float)cnt;
}

// ---------------- launch ------------------------------------------------------
extern "C" void kernel_launch(void* const* d_in, const int* in_sizes, int n_in,
                              void* d_out, int out_size) {
    const float* x        = (const float*)d_in[0];
    const int*   dist     = (const int*)  d_in[1];
    const float* base_rpr = (const float*)d_in[2];
    const float* w_q      = (const float*)d_in[3];
    const float* w_k      = (const float*)d_in[4];
    const float* w_v      = (const float*)d_in[5];
    const float* w_fc     = (const float*)d_in[6];
    const float* ln_g     = (const float*)d_in[7];
    const float* ln_b     = (const float*)d_in[8];

    float* x_out = (float*)d_out;
    float* attn  = x_out + (size_t)B_ * DM_ * E_;
    float* ape   = attn  + (size_t)B_ * H_ * E_ * E_;

    float* ds;  cudaGetSymbolAddress((void**)&ds,  g_s);
    float* dqn; cudaGetSymbolAddress((void**)&dqn, g_qn);

    k_transpose<<<dim3(E_ / 32, DM_ / 32, B_), dim3(32, 8)>>>(x);
    k_layernorm<<<B_ * E_, 256>>>(ln_g, ln_b);
    k_pack<<<(B_ * E_ * E_) / 1024, 256>>>(dist);

    k_qkv_mma<<<dim3(E_ / 128, 24, B_), 256>>>(dqn, ds, w_q, w_k, w_v);

    k_flash<<<dim3(32, B_ * H_), 256>>>(base_rpr, attn);
    k_fixup<<<B_ * H_ * 16, 256>>>(attn);
    k_fc_mma<<<dim3(B_ * E_ / 128, DM_ / 64, 1), 256>>>(w_fc, x_out);
    k_ape_final<<<(B_ * E_) / 256, 256>>>(ape);
}

// round 10
// speedup vs baseline: 1.9766x; 1.1094x over previous
#include <cuda_runtime.h>
#include <math.h>

#define B_  2
#define E_  1024
#define DM_ 512
#define H_  8
#define DK_ 64
#define DV_ 64
#define MAXN_ 5
#define NEGV (-1e9f)

__device__ __forceinline__ float tf32q(float x) {
    unsigned u;
    asm("cvt.rna.tf32.f32 %0, %1;" : "=r"(u) : "f"(x));
    return __uint_as_float(u);
}
__device__ __forceinline__ float4 tf32q4(float4 v) {
    v.x = tf32q(v.x); v.y = tf32q(v.y); v.z = tf32q(v.z); v.w = tf32q(v.w);
    return v;
}

#define MMA8(d, a, b)                                                        \
    asm volatile(                                                            \
        "mma.sync.aligned.m16n8k8.row.col.f32.tf32.tf32.f32 "                \
        "{%0,%1,%2,%3}, {%4,%5,%6,%7}, {%8,%9}, {%0,%1,%2,%3};\n"            \
        : "+f"((d)[0]), "+f"((d)[1]), "+f"((d)[2]), "+f"((d)[3])             \
        : "r"((a)[0]), "r"((a)[1]), "r"((a)[2]), "r"((a)[3]),                \
          "r"((b)[0]), "r"((b)[1]));

#define CP_ASYNC16(su, gp)                                                   \
    asm volatile("cp.async.cg.shared.global [%0], [%1], 16;\n"               \
                 :: "r"(su), "l"(gp) : "memory")
#define CP_COMMIT  asm volatile("cp.async.commit_group;\n" ::: "memory")
#define CP_WAIT0   asm volatile("cp.async.wait_group 0;\n" ::: "memory")

// ---------------- scratch ---------------------------------------------------
__device__ float g_s [B_*E_*DM_];
__device__ float g_qn[B_*E_*DM_];
__device__ float g_q [B_*H_*E_*DK_];     // tf32-rounded
__device__ float g_k [B_*H_*E_*DK_];     // tf32-rounded
__device__ float g_v [B_*H_*E_*DV_];     // tf32-rounded
__device__ float g_o [B_*E_*H_*DV_];
__device__ float g_pcs2[B_*H_*16*E_];
__device__ unsigned char g_d8[B_*E_*E_];

// ---------------- 1. transpose x[b,d,e] -> s[b,e,d] ------------------------
__global__ void k_transpose(const float* __restrict__ x) {
    __shared__ float tile[32][33];
    int b = blockIdx.z;
    int e0 = blockIdx.x * 32;
    int d0 = blockIdx.y * 32;
    int tx = threadIdx.x, ty = threadIdx.y;
#pragma unroll
    for (int r = 0; r < 4; r++) {
        int d = d0 + ty + r * 8;
        tile[ty + r * 8][tx] = x[(size_t)b * DM_ * E_ + (size_t)d * E_ + e0 + tx];
    }
    __syncthreads();
#pragma unroll
    for (int r = 0; r < 4; r++) {
        int e = e0 + ty + r * 8;
        g_s[(size_t)b * E_ * DM_ + (size_t)e * DM_ + d0 + tx] = tile[tx][ty + r * 8];
    }
}

// ---------------- 2. LayerNorm ----------------------------------------------
__global__ void k_layernorm(const float* __restrict__ ln_g, const float* __restrict__ ln_b) {
    int row = blockIdx.x;
    const float* src = g_s + (size_t)row * DM_;
    int tid = threadIdx.x;
    float2 v = ((const float2*)src)[tid];
    float s1 = v.x + v.y;
    float s2 = v.x * v.x + v.y * v.y;
#pragma unroll
    for (int o = 16; o; o >>= 1) {
        s1 += __shfl_xor_sync(0xffffffff, s1, o);
        s2 += __shfl_xor_sync(0xffffffff, s2, o);
    }
    __shared__ float sh[16];
    __shared__ float s_mu, s_rstd;
    int w = tid >> 5, l = tid & 31;
    if (l == 0) { sh[w] = s1; sh[8 + w] = s2; }
    __syncthreads();
    if (tid == 0) {
        float a = 0.f, c = 0.f;
#pragma unroll
        for (int i = 0; i < 8; i++) { a += sh[i]; c += sh[8 + i]; }
        float mu  = a / (float)DM_;
        float var = c / (float)DM_ - mu * mu;
        s_mu = mu;
        s_rstd = 1.f / sqrtf(var + 1e-6f);
    }
    __syncthreads();
    float mu = s_mu, rstd = s_rstd;
    float2 gg = ((const float2*)ln_g)[tid];
    float2 bb = ((const float2*)ln_b)[tid];
    float2 o;
    o.x = (v.x - mu) * rstd * gg.x + bb.x;
    o.y = (v.y - mu) * rstd * gg.y + bb.y;
    ((float2*)(g_qn + (size_t)row * DM_))[tid] = o;
}

// ---------------- 3. fused QKV GEMM (tensor core, tf32-rounded store) --------
__global__ __launch_bounds__(256) void k_qkv_mma(
    const float* __restrict__ A0, const float* __restrict__ A1,
    const float* __restrict__ Wq, const float* __restrict__ Wk,
    const float* __restrict__ Wv)
{
    __shared__ float As[128 * 36];
    __shared__ float Ws[32 * 72];
    int mat = blockIdx.y >> 3, h = blockIdx.y & 7, b = blockIdx.z;
    int m0 = blockIdx.x * 128;
    const float* A = (mat == 0) ? A0 : A1;
    const float* W = (mat == 0) ? Wq : (mat == 1 ? Wk : Wv);
    float* out = (mat == 0) ? g_q : (mat == 1 ? g_k : g_v);
    float scale = (mat == 0) ? 0.125f : 1.0f;

    int tid = threadIdx.x;
    int wid = tid >> 5, lane = tid & 31;
    int g = lane >> 2, t = lane & 3;
    int warpM = wid & 3, warpN = wid >> 2;

    const unsigned* Asu = (const unsigned*)As;
    const unsigned* Wsu = (const unsigned*)Ws;
    float acc[2][4][4] = {};
    size_t arow_base = ((size_t)b * E_ + m0);

    for (int k0 = 0; k0 < DM_; k0 += 32) {
        __syncthreads();
#pragma unroll
        for (int i = 0; i < 4; i++) {
            int f = tid + i * 256;
            int row = f >> 3, c4 = (f & 7) * 4;
            float4 v = tf32q4(*(const float4*)(A + (arow_base + row) * DM_ + k0 + c4));
            *(float4*)&As[row * 36 + c4] = v;
        }
#pragma unroll
        for (int i = 0; i < 2; i++) {
            int f = tid + i * 256;
            int row = f >> 4, c4 = (f & 15) * 4;
            float4 v = tf32q4(*(const float4*)(W + (size_t)(k0 + row) * (H_ * DK_) + h * 64 + c4));
            *(float4*)&Ws[row * 72 + c4] = v;
        }
        __syncthreads();
#pragma unroll
        for (int kk = 0; kk < 4; kk++) {
            int k = kk * 8;
            unsigned af[2][4], bf[4][2];
#pragma unroll
            for (int mb = 0; mb < 2; mb++) {
                int rb = warpM * 32 + mb * 16;
                af[mb][0] = Asu[(rb + g) * 36 + k + t];
                af[mb][1] = Asu[(rb + g + 8) * 36 + k + t];
                af[mb][2] = Asu[(rb + g) * 36 + k + t + 4];
                af[mb][3] = Asu[(rb + g + 8) * 36 + k + t + 4];
            }
#pragma unroll
            for (int nb = 0; nb < 4; nb++) {
                int cb = warpN * 32 + nb * 8 + g;
                bf[nb][0] = Wsu[(k + t) * 72 + cb];
                bf[nb][1] = Wsu[(k + t + 4) * 72 + cb];
            }
#pragma unroll
            for (int mb = 0; mb < 2; mb++)
#pragma unroll
                for (int nb = 0; nb < 4; nb++) MMA8(acc[mb][nb], af[mb], bf[nb])
        }
    }
    size_t obase = (((size_t)b * H_ + h) * E_ + m0) * 64;
#pragma unroll
    for (int mb = 0; mb < 2; mb++) {
        int r0 = warpM * 32 + mb * 16 + g;
#pragma unroll
        for (int nb = 0; nb < 4; nb++) {
            int c = warpN * 32 + nb * 8 + 2 * t;
            *(float2*)(out + obase + (size_t)r0 * 64 + c) =
                make_float2(tf32q(acc[mb][nb][0] * scale), tf32q(acc[mb][nb][1] * scale));
            *(float2*)(out + obase + (size_t)(r0 + 8) * 64 + c) =
                make_float2(tf32q(acc[mb][nb][2] * scale), tf32q(acc[mb][nb][3] * scale));
        }
    }
}

// ---------------- 4. pack dist -> int8 (clipped) -----------------------------
__global__ void k_pack(const int* __restrict__ dist) {
    int idx = blockIdx.x * 256 + threadIdx.x;
    int4 v = ((const int4*)dist)[idx];
    uchar4 o;
    o.x = (unsigned char)(v.x > 7 ? 7 : v.x);
    o.y = (unsigned char)(v.y > 7 ? 7 : v.y);
    o.z = (unsigned char)(v.z > 7 ? 7 : v.z);
    o.w = (unsigned char)(v.w > 7 ? 7 : v.w);
    ((uchar4*)g_d8)[idx] = o;
}

// ---------------- 5. flash: QK+softmax+O, double-buffered, fused fixup --------
// grid (16, B*H): block owns 64 i-rows. 8 warps: 4(warpM, 16 rows) x 2(warpN, 32 cols).
// Dynamic smem layout (floats):
//   Qs[64*68] @0, KP0 @4352, KP1 @8704, Vs0[64*72] @13056, Vs1 @17664,
//   rpr @22272(384), qrs @22656(384), musd[64*16] @23040,
//   rowm[64*2] @24064, rowl[64*2] @24192, mfin[64] @24320, linv[64] @24384
#define SM_QS    0
#define SM_KP0   4352
#define SM_KP1   8704
#define SM_VS0   13056
#define SM_VS1   17664
#define SM_RPR   22272
#define SM_QRS   22656
#define SM_MUSD  23040
#define SM_ROWM  24064
#define SM_ROWL  24192
#define SM_MFIN  24320
#define SM_LINV  24384
#define SM_TOTAL 24448   // floats -> 97792 bytes

__global__ __launch_bounds__(256) void k_flash(
    const float* __restrict__ base_rpr, float* __restrict__ attn)
{
    extern __shared__ float sm[];
    float* Qs     = sm + SM_QS;
    float* rpr_s  = sm + SM_RPR;
    float* qrs    = sm + SM_QRS;
    float* musd   = sm + SM_MUSD;
    float* rowm   = sm + SM_ROWM;
    float* rowl   = sm + SM_ROWL;
    float* mfin_s = sm + SM_MFIN;
    float* linv_s = sm + SM_LINV;
    float* KPb[2] = { sm + SM_KP0, sm + SM_KP1 };
    float* Vsb[2] = { sm + SM_VS0, sm + SM_VS1 };
    unsigned kp_u[2] = { (unsigned)__cvta_generic_to_shared(KPb[0]),
                         (unsigned)__cvta_generic_to_shared(KPb[1]) };
    unsigned vs_u[2] = { (unsigned)__cvta_generic_to_shared(Vsb[0]),
                         (unsigned)__cvta_generic_to_shared(Vsb[1]) };

    int iblk = blockIdx.x, i0 = iblk * 64;
    int z = blockIdx.y, b = z >> 3;
    int tid = threadIdx.x, wid = tid >> 5, lane = tid & 31;
    int g = lane >> 2, t = lane & 3;
    int warpM = wid & 3, warpN = wid >> 2;    // 4 x 2

    const unsigned* Qsu = (const unsigned*)Qs;

    size_t qbase = ((size_t)z * E_ + i0) * 64;
    size_t kvbase = (size_t)z * E_ * 64;
    const unsigned char* dbase = g_d8 + (size_t)b * E_ * E_;
    float* abase = attn + (size_t)z * E_ * E_;

    // prologue: Q tile (already tf32), rpr, qr table
#pragma unroll
    for (int i = 0; i < 4; i++) {
        int f = tid + i * 256;
        int row = f >> 4, c4 = (f & 15) * 4;
        *(float4*)&Qs[row * 68 + c4] =
            *(const float4*)(g_q + qbase + (size_t)row * 64 + c4);
    }
    for (int tt = tid; tt < 384; tt += 256) rpr_s[tt] = tf32q(base_rpr[tt]);

    // preload tile 0
    {
        const float* kg = g_k + kvbase;
        const float* vg = g_v + kvbase;
#pragma unroll
        for (int i = 0; i < 4; i++) {
            int f = tid + i * 256;
            int row = f >> 4, c4 = (f & 15) * 4;
            CP_ASYNC16(kp_u[0] + (unsigned)(row * 68 + c4) * 4, kg + row * 64 + c4);
            CP_ASYNC16(vs_u[0] + (unsigned)(row * 72 + c4) * 4, vg + row * 64 + c4);
        }
        CP_COMMIT;
    }
    __syncthreads();
    for (int tt = tid; tt < 384; tt += 256) {
        int row = tt / 6, c = tt % 6;
        float s = 0.f;
#pragma unroll 16
        for (int d = 0; d < 64; d++) s += Qs[row * 68 + d] * rpr_s[c * 64 + d];
        qrs[tt] = s;
    }

    int il0 = warpM * 16 + g, il1 = il0 + 8;
    int gi0 = i0 + il0, gi1 = i0 + il1;

    float m[2] = {-3.0e38f, -3.0e38f}, l[2] = {0.f, 0.f};
    float oacc[4][4] = {};
    int cur = 0;

    for (int jt = 0; jt < 16; jt++) {
        int j0 = jt * 64;
        CP_WAIT0;
        __syncthreads();                       // buf[cur] ready; qrs ready (jt=0)
        if (jt < 15) {                         // issue next tile into buf[cur^1]
            const float* kg = g_k + kvbase + (size_t)(j0 + 64) * 64;
            const float* vg = g_v + kvbase + (size_t)(j0 + 64) * 64;
            unsigned kb = kp_u[cur ^ 1], vb = vs_u[cur ^ 1];
#pragma unroll
            for (int i = 0; i < 4; i++) {
                int f = tid + i * 256;
                int row = f >> 4, c4 = (f & 15) * 4;
                CP_ASYNC16(kb + (unsigned)(row * 68 + c4) * 4, kg + row * 64 + c4);
                CP_ASYNC16(vb + (unsigned)(row * 72 + c4) * 4, vg + row * 64 + c4);
            }
            CP_COMMIT;
        }
        const unsigned* KPu = (const unsigned*)KPb[cur];
        const unsigned* Vsu = (const unsigned*)Vsb[cur];
        // QK mma: 16 rows x 64 cols per warp
        float acc[4][4] = {};
#pragma unroll
        for (int kk = 0; kk < 8; kk++) {
            int k = kk * 8;
            unsigned af[4];
            int rb = warpM * 16;
            af[0] = Qsu[(rb + g) * 68 + k + t];
            af[1] = Qsu[(rb + g + 8) * 68 + k + t];
            af[2] = Qsu[(rb + g) * 68 + k + t + 4];
            af[3] = Qsu[(rb + g + 8) * 68 + k + t + 4];
#pragma unroll
            for (int nb = 0; nb < 4; nb++) {
                unsigned bf[2];
                int cb = warpN * 32 + nb * 8 + g;
                bf[0] = KPu[cb * 68 + k + t];
                bf[1] = KPu[cb * 68 + k + t + 4];
                MMA8(acc[nb], af, bf)
            }
        }
        // x = acc + qr[dist] (masked), tile row max
        float tm0 = -3.0e38f, tm1 = -3.0e38f;
#pragma unroll
        for (int nb = 0; nb < 4; nb++) {
            int j = j0 + warpN * 32 + nb * 8 + 2 * t;
            uchar2 d0 = *(const uchar2*)(dbase + (size_t)gi0 * E_ + j);
            uchar2 d1 = *(const uchar2*)(dbase + (size_t)gi1 * E_ + j);
            acc[nb][0] = (d0.x <= MAXN_) ? acc[nb][0] + qrs[il0 * 6 + d0.x] : NEGV;
            acc[nb][1] = (d0.y <= MAXN_) ? acc[nb][1] + qrs[il0 * 6 + d0.y] : NEGV;
            acc[nb][2] = (d1.x <= MAXN_) ? acc[nb][2] + qrs[il1 * 6 + d1.x] : NEGV;
            acc[nb][3] = (d1.y <= MAXN_) ? acc[nb][3] + qrs[il1 * 6 + d1.y] : NEGV;
            tm0 = fmaxf(tm0, fmaxf(acc[nb][0], acc[nb][1]));
            tm1 = fmaxf(tm1, fmaxf(acc[nb][2], acc[nb][3]));
        }
#pragma unroll
        for (int off = 1; off < 4; off <<= 1) {
            tm0 = fmaxf(tm0, __shfl_xor_sync(0xffffffff, tm0, off));
            tm1 = fmaxf(tm1, __shfl_xor_sync(0xffffffff, tm1, off));
        }
        if (t == 0) { rowm[il0 * 2 + warpN] = tm0; rowm[il1 * 2 + warpN] = tm1; }
        __syncthreads();                        // also ends QK reads of KP[cur]
        float nm0 = fmaxf(m[0], fmaxf(rowm[il0 * 2], rowm[il0 * 2 + 1]));
        float nm1 = fmaxf(m[1], fmaxf(rowm[il1 * 2], rowm[il1 * 2 + 1]));
        float sc0 = __expf(m[0] - nm0), sc1 = __expf(m[1] - nm1);
        m[0] = nm0; m[1] = nm1;
        l[0] *= sc0; l[1] *= sc1;
#pragma unroll
        for (int nb = 0; nb < 4; nb++) {
            oacc[nb][0] *= sc0; oacc[nb][1] *= sc0;
            oacc[nb][2] *= sc1; oacc[nb][3] *= sc1;
        }
        float* KPw = KPb[cur];
#pragma unroll
        for (int nb = 0; nb < 4; nb++) {
            int jl = warpN * 32 + nb * 8 + 2 * t;
            int j = j0 + jl;
            float p00 = __expf(acc[nb][0] - nm0);
            float p01 = __expf(acc[nb][1] - nm0);
            float p10 = __expf(acc[nb][2] - nm1);
            float p11 = __expf(acc[nb][3] - nm1);
            l[0] += p00 + p01;
            l[1] += p10 + p11;
            *(float2*)(abase + (size_t)gi0 * E_ + j) = make_float2(p00, p01);
            *(float2*)(abase + (size_t)gi1 * E_ + j) = make_float2(p10, p11);
            KPw[il0 * 68 + jl]     = tf32q(p00);
            KPw[il0 * 68 + jl + 1] = tf32q(p01);
            KPw[il1 * 68 + jl]     = tf32q(p10);
            KPw[il1 * 68 + jl + 1] = tf32q(p11);
        }
        if (warpN == 0 && t == 0) {
            musd[il0 * 16 + jt] = nm0;
            musd[il1 * 16 + jt] = nm1;
        }
        __syncthreads();                        // P tile ready in KP[cur]
        // O += P(64 x 64) @ V(64 x 64)
#pragma unroll
        for (int kk = 0; kk < 8; kk++) {
            int k = kk * 8;
            unsigned af[4];
            int rb = warpM * 16;
            af[0] = KPu[(rb + g) * 68 + k + t];
            af[1] = KPu[(rb + g + 8) * 68 + k + t];
            af[2] = KPu[(rb + g) * 68 + k + t + 4];
            af[3] = KPu[(rb + g + 8) * 68 + k + t + 4];
#pragma unroll
            for (int nb = 0; nb < 4; nb++) {
                unsigned bf[2];
                int cb = warpN * 32 + nb * 8 + g;
                bf[0] = Vsu[(k + t) * 72 + cb];
                bf[1] = Vsu[(k + t + 4) * 72 + cb];
                MMA8(oacc[nb], af, bf)
            }
        }
        cur ^= 1;
    }
    // final l reduce -> linv, mfin
#pragma unroll
    for (int off = 1; off < 4; off <<= 1) {
        l[0] += __shfl_xor_sync(0xffffffff, l[0], off);
        l[1] += __shfl_xor_sync(0xffffffff, l[1], off);
    }
    if (t == 0) {
        rowl[il0 * 2 + warpN] = l[0];
        rowl[il1 * 2 + warpN] = l[1];
        if (warpN == 0) { mfin_s[il0] = m[0]; mfin_s[il1] = m[1]; }
    }
    __syncthreads();
    if (tid < 64) linv_s[tid] = 1.f / (rowl[tid * 2] + rowl[tid * 2 + 1]);
    __syncthreads();
    // O write
    float inv0 = linv_s[il0], inv1 = linv_s[il1];
    int h = z & 7;
#pragma unroll
    for (int nb = 0; nb < 4; nb++) {
        int dv = h * 64 + warpN * 32 + nb * 8 + 2 * t;
        *(float2*)(g_o + ((size_t)b * E_ + gi0) * 512 + dv) =
            make_float2(oacc[nb][0] * inv0, oacc[nb][1] * inv0);
        *(float2*)(g_o + ((size_t)b * E_ + gi1) * 512 + dv) =
            make_float2(oacc[nb][2] * inv1, oacc[nb][3] * inv1);
    }
    // transform musd -> per (row,tile) rescale factor
#pragma unroll
    for (int k = 0; k < 4; k++) {
        int idx = tid + k * 256;
        int row = idx >> 4;
        musd[idx] = __expf(musd[idx] - mfin_s[row]) * linv_s[row];
    }
    __syncthreads();
    // fused fixup: rescale own 64x1024 rows (L2-hot) + ape column partials
    {
        int j = tid * 4;
        int tile = tid >> 4;
        float4 cs = make_float4(0.f, 0.f, 0.f, 0.f);
        float* arow = abase + (size_t)i0 * E_ + j;
#pragma unroll 4
        for (int r = 0; r < 64; r++) {
            float fac = musd[r * 16 + tile];
            float4 x = *(float4*)(arow + (size_t)r * E_);
            x.x *= fac; x.y *= fac; x.z *= fac; x.w *= fac;
            *(float4*)(arow + (size_t)r * E_) = x;
            cs.x += x.x; cs.y += x.y; cs.z += x.z; cs.w += x.w;
        }
        *(float4*)(g_pcs2 + ((size_t)z * 16 + iblk) * E_ + j) = cs;
    }
}

// ---------------- 6. FC + residual + transposed store (tensor core) ----------
__global__ __launch_bounds__(256) void k_fc_mma(
    const float* __restrict__ w_fc, float* __restrict__ xout)
{
    __shared__ float sm2[64 * 132];
    float* As = sm2;
    float* Ws = sm2 + 128 * 36;
    int m0 = blockIdx.x * 128, n0 = blockIdx.y * 64;
    int b = m0 >> 10, e0 = m0 & 1023;
    int tid = threadIdx.x;
    int wid = tid >> 5, lane = tid & 31;
    int g = lane >> 2, t = lane & 3;
    int warpM = wid & 3, warpN = wid >> 2;

    const unsigned* Asu = (const unsigned*)As;
    const unsigned* Wsu = (const unsigned*)Ws;
    float acc[2][4][4] = {};

    for (int k0 = 0; k0 < 512; k0 += 32) {
        __syncthreads();
#pragma unroll
        for (int i = 0; i < 4; i++) {
            int f = tid + i * 256;
            int row = f >> 3, c4 = (f & 7) * 4;
            float4 v = tf32q4(*(const float4*)(g_o + (size_t)(m0 + row) * 512 + k0 + c4));
            *(float4*)&As[row * 36 + c4] = v;
        }
#pragma unroll
        for (int i = 0; i < 2; i++) {
            int f = tid + i * 256;
            int row = f >> 4, c4 = (f & 15) * 4;
            float4 v = tf32q4(*(const float4*)(w_fc + (size_t)(k0 + row) * DM_ + n0 + c4));
            *(float4*)&Ws[row * 72 + c4] = v;
        }
        __syncthreads();
#pragma unroll
        for (int kk = 0; kk < 4; kk++) {
            int k = kk * 8;
            unsigned af[2][4], bf[4][2];
#pragma unroll
            for (int mb = 0; mb < 2; mb++) {
                int rb = warpM * 32 + mb * 16;
                af[mb][0] = Asu[(rb + g) * 36 + k + t];
                af[mb][1] = Asu[(rb + g + 8) * 36 + k + t];
                af[mb][2] = Asu[(rb + g) * 36 + k + t + 4];
                af[mb][3] = Asu[(rb + g + 8) * 36 + k + t + 4];
            }
#pragma unroll
            for (int nb = 0; nb < 4; nb++) {
                int cb = warpN * 32 + nb * 8 + g;
                bf[nb][0] = Wsu[(k + t) * 72 + cb];
                bf[nb][1] = Wsu[(k + t + 4) * 72 + cb];
            }
#pragma unroll
            for (int mb = 0; mb < 2; mb++)
#pragma unroll
                for (int nb = 0; nb < 4; nb++) MMA8(acc[mb][nb], af[mb], bf[nb])
        }
    }
    __syncthreads();
#pragma unroll
    for (int mb = 0; mb < 2; mb++) {
        int el0 = warpM * 32 + mb * 16 + g;
#pragma unroll
        for (int nb = 0; nb < 4; nb++) {
            int nl = warpN * 32 + nb * 8 + 2 * t;
#pragma unroll
            for (int half = 0; half < 2; half++) {
                int el = el0 + half * 8;
                const float* res = g_s + (size_t)(m0 + el) * DM_ + n0 + nl;
                sm2[(nl + 0) * 132 + el] = acc[mb][nb][half * 2 + 0] + res[0];
                sm2[(nl + 1) * 132 + el] = acc[mb][nb][half * 2 + 1] + res[1];
            }
        }
    }
    __syncthreads();
#pragma unroll
    for (int i = 0; i < 8; i++) {
        int f = tid + i * 256;
        int row = f >> 5, c4 = (f & 31) * 4;
        float4 v = *(const float4*)&sm2[row * 132 + c4];
        *(float4*)(xout + ((size_t)b * DM_ + n0 + row) * E_ + e0 + c4) = v;
    }
}

// ---------------- 7. ape final -------------------------------------------------
__global__ void k_ape_final(float* __restrict__ ape) {
    int idx = blockIdx.x * 256 + threadIdx.x;
    int b = idx >> 10, j = idx & (E_ - 1);
    float cs = 0.f;
    const float* p = g_pcs2 + (size_t)b * 8 * 16 * E_ + j;
#pragma unroll 8
    for (int k = 0; k < 128; k++) cs += p[(size_t)k * E_];
    const unsigned char* dcol = g_d8 + (size_t)b * E_ * E_ + j;
    int cnt = 0;
#pragma unroll 8
    for (int i = 0; i < E_; i++) cnt += (dcol[(size_t)i * E_] <= MAXN_) ? 1 : 0;
    ape[idx] = cs / (float)cnt;
}

// ---------------- launch ------------------------------------------------------
extern "C" void kernel_launch(void* const* d_in, const int* in_sizes, int n_in,
                              void* d_out, int out_size) {
    const float* x        = (const float*)d_in[0];
    const int*   dist     = (const int*)  d_in[1];
    const float* base_rpr = (const float*)d_in[2];
    const float* w_q      = (const float*)d_in[3];
    const float* w_k      = (const float*)d_in[4];
    const float* w_v      = (const float*)d_in[5];
    const float* w_fc     = (const float*)d_in[6];
    const float* ln_g     = (const float*)d_in[7];
    const float* ln_b     = (const float*)d_in[8];

    float* x_out = (float*)d_out;
    float* attn  = x_out + (size_t)B_ * DM_ * E_;
    float* ape   = attn  + (size_t)B_ * H_ * E_ * E_;

    float* ds;  cudaGetSymbolAddress((void**)&ds,  g_s);
    float* dqn; cudaGetSymbolAddress((void**)&dqn, g_qn);

    static int smem_set = 0;
    if (!smem_set) {
        cudaFuncSetAttribute(k_flash, cudaFuncAttributeMaxDynamicSharedMemorySize,
                             SM_TOTAL * 4);
        smem_set = 1;
    }

    k_transpose<<<dim3(E_ / 32, DM_ / 32, B_), dim3(32, 8)>>>(x);
    k_layernorm<<<B_ * E_, 256>>>(ln_g, ln_b);
    k_pack<<<(B_ * E_ * E_) / 1024, 256>>>(dist);

    k_qkv_mma<<<dim3(E_ / 128, 24, B_), 256>>>(dqn, ds, w_q, w_k, w_v);

    k_flash<<<dim3(16, B_ * H_), 256, SM_TOTAL * 4>>>(base_rpr, attn);
    k_fc_mma<<<dim3(B_ * E_ / 128, DM_ / 64, 1), 256>>>(w_fc, x_out);
    k_ape_final<<<(B_ * E_) / 256, 256>>>(ape);
}

// round 11
// speedup vs baseline: 2.0079x; 1.0159x over previous
#include <cuda_runtime.h>
#include <math.h>

#define B_  2
#define E_  1024
#define DM_ 512
#define H_  8
#define DK_ 64
#define DV_ 64
#define MAXN_ 5
#define NEGV (-1e9f)

__device__ __forceinline__ float tf32q(float x) {
    unsigned u;
    asm("cvt.rna.tf32.f32 %0, %1;" : "=r"(u) : "f"(x));
    return __uint_as_float(u);
}
__device__ __forceinline__ float4 tf32q4(float4 v) {
    v.x = tf32q(v.x); v.y = tf32q(v.y); v.z = tf32q(v.z); v.w = tf32q(v.w);
    return v;
}

#define MMA8(d, a, b)                                                        \
    asm volatile(                                                            \
        "mma.sync.aligned.m16n8k8.row.col.f32.tf32.tf32.f32 "                \
        "{%0,%1,%2,%3}, {%4,%5,%6,%7}, {%8,%9}, {%0,%1,%2,%3};\n"            \
        : "+f"((d)[0]), "+f"((d)[1]), "+f"((d)[2]), "+f"((d)[3])             \
        : "r"((a)[0]), "r"((a)[1]), "r"((a)[2]), "r"((a)[3]),                \
          "r"((b)[0]), "r"((b)[1]));

#define CP_ASYNC16(su, gp)                                                   \
    asm volatile("cp.async.cg.shared.global [%0], [%1], 16;\n"               \
                 :: "r"(su), "l"(gp) : "memory")
#define CP_COMMIT  asm volatile("cp.async.commit_group;\n" ::: "memory")
#define CP_WAIT0   asm volatile("cp.async.wait_group 0;\n" ::: "memory")

// ---------------- scratch ---------------------------------------------------
__device__ float g_s  [B_*E_*DM_];       // exact (LN stats + FC residual)
__device__ float g_sq [B_*E_*DM_];       // tf32-rounded (K/V GEMM input)
__device__ float g_qn [B_*E_*DM_];       // LN output, tf32-rounded
__device__ float g_q  [B_*H_*E_*DK_];    // tf32-rounded
__device__ float g_k  [B_*H_*E_*DK_];    // tf32-rounded
__device__ float g_v  [B_*H_*E_*DV_];    // tf32-rounded
__device__ float g_o  [B_*E_*H_*DV_];    // tf32-rounded
__device__ float g_wq  [3*DM_*(H_*DK_)]; // quantized w_q|w_k|w_v
__device__ float g_wfcq[DM_*DM_];        // quantized w_fc
__device__ float g_pcs2[B_*H_*16*E_];
__device__ unsigned char g_d8[B_*E_*E_];

// ---------------- 1. transpose x[b,d,e] -> s[b,e,d] (+tf32 copy) ------------
__global__ void k_transpose(const float* __restrict__ x) {
    __shared__ float tile[32][33];
    int b = blockIdx.z;
    int e0 = blockIdx.x * 32;
    int d0 = blockIdx.y * 32;
    int tx = threadIdx.x, ty = threadIdx.y;
#pragma unroll
    for (int r = 0; r < 4; r++) {
        int d = d0 + ty + r * 8;
        tile[ty + r * 8][tx] = x[(size_t)b * DM_ * E_ + (size_t)d * E_ + e0 + tx];
    }
    __syncthreads();
#pragma unroll
    for (int r = 0; r < 4; r++) {
        int e = e0 + ty + r * 8;
        float v = tile[tx][ty + r * 8];
        size_t idx = (size_t)b * E_ * DM_ + (size_t)e * DM_ + d0 + tx;
        g_s[idx]  = v;
        g_sq[idx] = tf32q(v);
    }
}

// ---------------- 2. LayerNorm (tf32-rounded output) -------------------------
__global__ void k_layernorm(const float* __restrict__ ln_g, const float* __restrict__ ln_b) {
    int row = blockIdx.x;
    const float* src = g_s + (size_t)row * DM_;
    int tid = threadIdx.x;
    float2 v = ((const float2*)src)[tid];
    float s1 = v.x + v.y;
    float s2 = v.x * v.x + v.y * v.y;
#pragma unroll
    for (int o = 16; o; o >>= 1) {
        s1 += __shfl_xor_sync(0xffffffff, s1, o);
        s2 += __shfl_xor_sync(0xffffffff, s2, o);
    }
    __shared__ float sh[16];
    __shared__ float s_mu, s_rstd;
    int w = tid >> 5, l = tid & 31;
    if (l == 0) { sh[w] = s1; sh[8 + w] = s2; }
    __syncthreads();
    if (tid == 0) {
        float a = 0.f, c = 0.f;
#pragma unroll
        for (int i = 0; i < 8; i++) { a += sh[i]; c += sh[8 + i]; }
        float mu  = a / (float)DM_;
        float var = c / (float)DM_ - mu * mu;
        s_mu = mu;
        s_rstd = 1.f / sqrtf(var + 1e-6f);
    }
    __syncthreads();
    float mu = s_mu, rstd = s_rstd;
    float2 gg = ((const float2*)ln_g)[tid];
    float2 bb = ((const float2*)ln_b)[tid];
    float2 o;
    o.x = tf32q((v.x - mu) * rstd * gg.x + bb.x);
    o.y = tf32q((v.y - mu) * rstd * gg.y + bb.y);
    ((float2*)(g_qn + (size_t)row * DM_))[tid] = o;
}

// ---------------- 3. pack dist -> int8 + quantize weights --------------------
__global__ void k_pack_prep(const int* __restrict__ dist,
                            const float* __restrict__ w_q,
                            const float* __restrict__ w_k,
                            const float* __restrict__ w_v,
                            const float* __restrict__ w_fc) {
    int bid = blockIdx.x;
    if (bid < 2048) {                    // pack: B*E*E/4 = 524288 uchar4
        int idx = bid * 256 + threadIdx.x;
        int4 v = ((const int4*)dist)[idx];
        uchar4 o;
        o.x = (unsigned char)(v.x > 7 ? 7 : v.x);
        o.y = (unsigned char)(v.y > 7 ? 7 : v.y);
        o.z = (unsigned char)(v.z > 7 ? 7 : v.z);
        o.w = (unsigned char)(v.w > 7 ? 7 : v.w);
        ((uchar4*)g_d8)[idx] = o;
    } else {                             // prep: 4 matrices x 65536 float4
        int idx = (bid - 2048) * 256 + threadIdx.x;
        int matid = idx >> 16;
        int off = idx & 65535;
        const float* src = (matid == 0) ? w_q : (matid == 1) ? w_k
                          : (matid == 2) ? w_v : w_fc;
        float4 v = tf32q4(((const float4*)src)[off]);
        float* dst = (matid < 3) ? (g_wq + (size_t)matid * DM_ * 512)
                                 : g_wfcq;
        ((float4*)dst)[off] = v;
    }
}

// ---------------- 4. fused QKV GEMM (cp.async double-buffered) ---------------
// dyn smem: As0 @0(4608), As1 @4608, Ws0 @9216(2304), Ws1 @11520; 13824 floats
#define QKV_SM 13824
__global__ __launch_bounds__(256) void k_qkv_mma() {
    extern __shared__ float qsm[];
    float* Ab[2] = { qsm, qsm + 4608 };
    float* Wb[2] = { qsm + 9216, qsm + 11520 };
    unsigned a_u[2] = { (unsigned)__cvta_generic_to_shared(Ab[0]),
                        (unsigned)__cvta_generic_to_shared(Ab[1]) };
    unsigned w_u[2] = { (unsigned)__cvta_generic_to_shared(Wb[0]),
                        (unsigned)__cvta_generic_to_shared(Wb[1]) };

    int mat = blockIdx.y >> 3, h = blockIdx.y & 7, b = blockIdx.z;
    int m0 = blockIdx.x * 128;
    const float* A = (mat == 0) ? g_qn : g_sq;
    const float* W = g_wq + (size_t)mat * DM_ * 512;
    float* out = (mat == 0) ? g_q : (mat == 1 ? g_k : g_v);
    float scale = (mat == 0) ? 0.125f : 1.0f;

    int tid = threadIdx.x;
    int wid = tid >> 5, lane = tid & 31;
    int g = lane >> 2, t = lane & 3;
    int warpM = wid & 3, warpN = wid >> 2;

    float acc[2][4][4] = {};
    size_t arow_base = ((size_t)b * E_ + m0);

    // preload chunk 0
    {
#pragma unroll
        for (int i = 0; i < 4; i++) {
            int f = tid + i * 256;
            int row = f >> 3, c4 = (f & 7) * 4;
            CP_ASYNC16(a_u[0] + (unsigned)(row * 36 + c4) * 4,
                       A + (arow_base + row) * DM_ + c4);
        }
#pragma unroll
        for (int i = 0; i < 2; i++) {
            int f = tid + i * 256;
            int row = f >> 4, c4 = (f & 15) * 4;
            CP_ASYNC16(w_u[0] + (unsigned)(row * 72 + c4) * 4,
                       W + (size_t)row * 512 + h * 64 + c4);
        }
        CP_COMMIT;
    }
    int cur = 0;
    for (int k0 = 0; k0 < DM_; k0 += 32) {
        CP_WAIT0;
        __syncthreads();
        if (k0 + 32 < DM_) {
            unsigned au = a_u[cur ^ 1], wu = w_u[cur ^ 1];
#pragma unroll
            for (int i = 0; i < 4; i++) {
                int f = tid + i * 256;
                int row = f >> 3, c4 = (f & 7) * 4;
                CP_ASYNC16(au + (unsigned)(row * 36 + c4) * 4,
                           A + (arow_base + row) * DM_ + k0 + 32 + c4);
            }
#pragma unroll
            for (int i = 0; i < 2; i++) {
                int f = tid + i * 256;
                int row = f >> 4, c4 = (f & 15) * 4;
                CP_ASYNC16(wu + (unsigned)(row * 72 + c4) * 4,
                           W + (size_t)(k0 + 32 + row) * 512 + h * 64 + c4);
            }
            CP_COMMIT;
        }
        const unsigned* Asu = (const unsigned*)Ab[cur];
        const unsigned* Wsu = (const unsigned*)Wb[cur];
#pragma unroll
        for (int kk = 0; kk < 4; kk++) {
            int k = kk * 8;
            unsigned af[2][4], bf[4][2];
#pragma unroll
            for (int mb = 0; mb < 2; mb++) {
                int rb = warpM * 32 + mb * 16;
                af[mb][0] = Asu[(rb + g) * 36 + k + t];
                af[mb][1] = Asu[(rb + g + 8) * 36 + k + t];
                af[mb][2] = Asu[(rb + g) * 36 + k + t + 4];
                af[mb][3] = Asu[(rb + g + 8) * 36 + k + t + 4];
            }
#pragma unroll
            for (int nb = 0; nb < 4; nb++) {
                int cb = warpN * 32 + nb * 8 + g;
                bf[nb][0] = Wsu[(k + t) * 72 + cb];
                bf[nb][1] = Wsu[(k + t + 4) * 72 + cb];
            }
#pragma unroll
            for (int mb = 0; mb < 2; mb++)
#pragma unroll
                for (int nb = 0; nb < 4; nb++) MMA8(acc[mb][nb], af[mb], bf[nb])
        }
        cur ^= 1;
    }
    size_t obase = (((size_t)b * H_ + h) * E_ + m0) * 64;
#pragma unroll
    for (int mb = 0; mb < 2; mb++) {
        int r0 = warpM * 32 + mb * 16 + g;
#pragma unroll
        for (int nb = 0; nb < 4; nb++) {
            int c = warpN * 32 + nb * 8 + 2 * t;
            *(float2*)(out + obase + (size_t)r0 * 64 + c) =
                make_float2(tf32q(acc[mb][nb][0] * scale), tf32q(acc[mb][nb][1] * scale));
            *(float2*)(out + obase + (size_t)(r0 + 8) * 64 + c) =
                make_float2(tf32q(acc[mb][nb][2] * scale), tf32q(acc[mb][nb][3] * scale));
        }
    }
}

// ---------------- 5. flash: QK+softmax+O, double-buffered, fused fixup --------
#define SM_QS    0
#define SM_KP0   4352
#define SM_KP1   8704
#define SM_VS0   13056
#define SM_VS1   17664
#define SM_RPR   22272
#define SM_QRS   22656
#define SM_MUSD  23040
#define SM_ROWM  24064
#define SM_ROWL  24192
#define SM_MFIN  24320
#define SM_LINV  24384
#define SM_TOTAL 24448   // floats

__global__ __launch_bounds__(256) void k_flash(
    const float* __restrict__ base_rpr, float* __restrict__ attn)
{
    extern __shared__ float sm[];
    float* Qs     = sm + SM_QS;
    float* rpr_s  = sm + SM_RPR;
    float* qrs    = sm + SM_QRS;
    float* musd   = sm + SM_MUSD;
    float* rowm   = sm + SM_ROWM;
    float* rowl   = sm + SM_ROWL;
    float* mfin_s = sm + SM_MFIN;
    float* linv_s = sm + SM_LINV;
    float* KPb[2] = { sm + SM_KP0, sm + SM_KP1 };
    float* Vsb[2] = { sm + SM_VS0, sm + SM_VS1 };
    unsigned kp_u[2] = { (unsigned)__cvta_generic_to_shared(KPb[0]),
                         (unsigned)__cvta_generic_to_shared(KPb[1]) };
    unsigned vs_u[2] = { (unsigned)__cvta_generic_to_shared(Vsb[0]),
                         (unsigned)__cvta_generic_to_shared(Vsb[1]) };

    int iblk = blockIdx.x, i0 = iblk * 64;
    int z = blockIdx.y, b = z >> 3;
    int tid = threadIdx.x, wid = tid >> 5, lane = tid & 31;
    int g = lane >> 2, t = lane & 3;
    int warpM = wid & 3, warpN = wid >> 2;

    const unsigned* Qsu = (const unsigned*)Qs;

    size_t qbase = ((size_t)z * E_ + i0) * 64;
    size_t kvbase = (size_t)z * E_ * 64;
    const unsigned char* dbase = g_d8 + (size_t)b * E_ * E_;
    float* abase = attn + (size_t)z * E_ * E_;

#pragma unroll
    for (int i = 0; i < 4; i++) {
        int f = tid + i * 256;
        int row = f >> 4, c4 = (f & 15) * 4;
        *(float4*)&Qs[row * 68 + c4] =
            *(const float4*)(g_q + qbase + (size_t)row * 64 + c4);
    }
    for (int tt = tid; tt < 384; tt += 256) rpr_s[tt] = tf32q(base_rpr[tt]);

    {
        const float* kg = g_k + kvbase;
        const float* vg = g_v + kvbase;
#pragma unroll
        for (int i = 0; i < 4; i++) {
            int f = tid + i * 256;
            int row = f >> 4, c4 = (f & 15) * 4;
            CP_ASYNC16(kp_u[0] + (unsigned)(row * 68 + c4) * 4, kg + row * 64 + c4);
            CP_ASYNC16(vs_u[0] + (unsigned)(row * 72 + c4) * 4, vg + row * 64 + c4);
        }
        CP_COMMIT;
    }
    __syncthreads();
    for (int tt = tid; tt < 384; tt += 256) {
        int row = tt / 6, c = tt % 6;
        float s = 0.f;
#pragma unroll 16
        for (int d = 0; d < 64; d++) s += Qs[row * 68 + d] * rpr_s[c * 64 + d];
        qrs[tt] = s;
    }

    int il0 = warpM * 16 + g, il1 = il0 + 8;
    int gi0 = i0 + il0, gi1 = i0 + il1;

    float m[2] = {-3.0e38f, -3.0e38f}, l[2] = {0.f, 0.f};
    float oacc[4][4] = {};
    int cur = 0;

    for (int jt = 0; jt < 16; jt++) {
        int j0 = jt * 64;
        CP_WAIT0;
        __syncthreads();
        if (jt < 15) {
            const float* kg = g_k + kvbase + (size_t)(j0 + 64) * 64;
            const float* vg = g_v + kvbase + (size_t)(j0 + 64) * 64;
            unsigned kb = kp_u[cur ^ 1], vb = vs_u[cur ^ 1];
#pragma unroll
            for (int i = 0; i < 4; i++) {
                int f = tid + i * 256;
                int row = f >> 4, c4 = (f & 15) * 4;
                CP_ASYNC16(kb + (unsigned)(row * 68 + c4) * 4, kg + row * 64 + c4);
                CP_ASYNC16(vb + (unsigned)(row * 72 + c4) * 4, vg + row * 64 + c4);
            }
            CP_COMMIT;
        }
        const unsigned* KPu = (const unsigned*)KPb[cur];
        const unsigned* Vsu = (const unsigned*)Vsb[cur];
        float acc[4][4] = {};
#pragma unroll
        for (int kk = 0; kk < 8; kk++) {
            int k = kk * 8;
            unsigned af[4];
            int rb = warpM * 16;
            af[0] = Qsu[(rb + g) * 68 + k + t];
            af[1] = Qsu[(rb + g + 8) * 68 + k + t];
            af[2] = Qsu[(rb + g) * 68 + k + t + 4];
            af[3] = Qsu[(rb + g + 8) * 68 + k + t + 4];
#pragma unroll
            for (int nb = 0; nb < 4; nb++) {
                unsigned bf[2];
                int cb = warpN * 32 + nb * 8 + g;
                bf[0] = KPu[cb * 68 + k + t];
                bf[1] = KPu[cb * 68 + k + t + 4];
                MMA8(acc[nb], af, bf)
            }
        }
        float tm0 = -3.0e38f, tm1 = -3.0e38f;
#pragma unroll
        for (int nb = 0; nb < 4; nb++) {
            int j = j0 + warpN * 32 + nb * 8 + 2 * t;
            uchar2 d0 = *(const uchar2*)(dbase + (size_t)gi0 * E_ + j);
            uchar2 d1 = *(const uchar2*)(dbase + (size_t)gi1 * E_ + j);
            acc[nb][0] = (d0.x <= MAXN_) ? acc[nb][0] + qrs[il0 * 6 + d0.x] : NEGV;
            acc[nb][1] = (d0.y <= MAXN_) ? acc[nb][1] + qrs[il0 * 6 + d0.y] : NEGV;
            acc[nb][2] = (d1.x <= MAXN_) ? acc[nb][2] + qrs[il1 * 6 + d1.x] : NEGV;
            acc[nb][3] = (d1.y <= MAXN_) ? acc[nb][3] + qrs[il1 * 6 + d1.y] : NEGV;
            tm0 = fmaxf(tm0, fmaxf(acc[nb][0], acc[nb][1]));
            tm1 = fmaxf(tm1, fmaxf(acc[nb][2], acc[nb][3]));
        }
#pragma unroll
        for (int off = 1; off < 4; off <<= 1) {
            tm0 = fmaxf(tm0, __shfl_xor_sync(0xffffffff, tm0, off));
            tm1 = fmaxf(tm1, __shfl_xor_sync(0xffffffff, tm1, off));
        }
        if (t == 0) { rowm[il0 * 2 + warpN] = tm0; rowm[il1 * 2 + warpN] = tm1; }
        __syncthreads();
        float nm0 = fmaxf(m[0], fmaxf(rowm[il0 * 2], rowm[il0 * 2 + 1]));
        float nm1 = fmaxf(m[1], fmaxf(rowm[il1 * 2], rowm[il1 * 2 + 1]));
        float sc0 = __expf(m[0] - nm0), sc1 = __expf(m[1] - nm1);
        m[0] = nm0; m[1] = nm1;
        l[0] *= sc0; l[1] *= sc1;
#pragma unroll
        for (int nb = 0; nb < 4; nb++) {
            oacc[nb][0] *= sc0; oacc[nb][1] *= sc0;
            oacc[nb][2] *= sc1; oacc[nb][3] *= sc1;
        }
        float* KPw = KPb[cur];
#pragma unroll
        for (int nb = 0; nb < 4; nb++) {
            int jl = warpN * 32 + nb * 8 + 2 * t;
            int j = j0 + jl;
            float p00 = __expf(acc[nb][0] - nm0);
            float p01 = __expf(acc[nb][1] - nm0);
            float p10 = __expf(acc[nb][2] - nm1);
            float p11 = __expf(acc[nb][3] - nm1);
            l[0] += p00 + p01;
            l[1] += p10 + p11;
            *(float2*)(abase + (size_t)gi0 * E_ + j) = make_float2(p00, p01);
            *(float2*)(abase + (size_t)gi1 * E_ + j) = make_float2(p10, p11);
            KPw[il0 * 68 + jl]     = tf32q(p00);
            KPw[il0 * 68 + jl + 1] = tf32q(p01);
            KPw[il1 * 68 + jl]     = tf32q(p10);
            KPw[il1 * 68 + jl + 1] = tf32q(p11);
        }
        if (warpN == 0 && t == 0) {
            musd[il0 * 16 + jt] = nm0;
            musd[il1 * 16 + jt] = nm1;
        }
        __syncthreads();
#pragma unroll
        for (int kk = 0; kk < 8; kk++) {
            int k = kk * 8;
            unsigned af[4];
            int rb = warpM * 16;
            af[0] = KPu[(rb + g) * 68 + k + t];
            af[1] = KPu[(rb + g + 8) * 68 + k + t];
            af[2] = KPu[(rb + g) * 68 + k + t + 4];
            af[3] = KPu[(rb + g + 8) * 68 + k + t + 4];
#pragma unroll
            for (int nb = 0; nb < 4; nb++) {
                unsigned bf[2];
                int cb = warpN * 32 + nb * 8 + g;
                bf[0] = Vsu[(k + t) * 72 + cb];
                bf[1] = Vsu[(k + t + 4) * 72 + cb];
                MMA8(oacc[nb], af, bf)
            }
        }
        cur ^= 1;
    }
#pragma unroll
    for (int off = 1; off < 4; off <<= 1) {
        l[0] += __shfl_xor_sync(0xffffffff, l[0], off);
        l[1] += __shfl_xor_sync(0xffffffff, l[1], off);
    }
    if (t == 0) {
        rowl[il0 * 2 + warpN] = l[0];
        rowl[il1 * 2 + warpN] = l[1];
        if (warpN == 0) { mfin_s[il0] = m[0]; mfin_s[il1] = m[1]; }
    }
    __syncthreads();
    if (tid < 64) linv_s[tid] = 1.f / (rowl[tid * 2] + rowl[tid * 2 + 1]);
    __syncthreads();
    float inv0 = linv_s[il0], inv1 = linv_s[il1];
    int h = z & 7;
#pragma unroll
    for (int nb = 0; nb < 4; nb++) {
        int dv = h * 64 + warpN * 32 + nb * 8 + 2 * t;
        *(float2*)(g_o + ((size_t)b * E_ + gi0) * 512 + dv) =
            make_float2(tf32q(oacc[nb][0] * inv0), tf32q(oacc[nb][1] * inv0));
        *(float2*)(g_o + ((size_t)b * E_ + gi1) * 512 + dv) =
            make_float2(tf32q(oacc[nb][2] * inv1), tf32q(oacc[nb][3] * inv1));
    }
#pragma unroll
    for (int k = 0; k < 4; k++) {
        int idx = tid + k * 256;
        int row = idx >> 4;
        musd[idx] = __expf(musd[idx] - mfin_s[row]) * linv_s[row];
    }
    __syncthreads();
    {
        int j = tid * 4;
        int tile = tid >> 4;
        float4 cs = make_float4(0.f, 0.f, 0.f, 0.f);
        float* arow = abase + (size_t)i0 * E_ + j;
#pragma unroll 4
        for (int r = 0; r < 64; r++) {
            float fac = musd[r * 16 + tile];
            float4 x = *(float4*)(arow + (size_t)r * E_);
            x.x *= fac; x.y *= fac; x.z *= fac; x.w *= fac;
            *(float4*)(arow + (size_t)r * E_) = x;
            cs.x += x.x; cs.y += x.y; cs.z += x.z; cs.w += x.w;
        }
        *(float4*)(g_pcs2 + ((size_t)z * 16 + iblk) * E_ + j) = cs;
    }
}

// ---------------- 6. FC + residual (cp.async double-buffered) ----------------
#define FC_SM 13824
__global__ __launch_bounds__(256) void k_fc_mma(float* __restrict__ xout) {
    extern __shared__ float fsm[];
    float* Ab[2] = { fsm, fsm + 4608 };
    float* Wb[2] = { fsm + 9216, fsm + 11520 };
    unsigned a_u[2] = { (unsigned)__cvta_generic_to_shared(Ab[0]),
                        (unsigned)__cvta_generic_to_shared(Ab[1]) };
    unsigned w_u[2] = { (unsigned)__cvta_generic_to_shared(Wb[0]),
                        (unsigned)__cvta_generic_to_shared(Wb[1]) };
    int m0 = blockIdx.x * 128, n0 = blockIdx.y * 64;
    int b = m0 >> 10, e0 = m0 & 1023;
    int tid = threadIdx.x;
    int wid = tid >> 5, lane = tid & 31;
    int g = lane >> 2, t = lane & 3;
    int warpM = wid & 3, warpN = wid >> 2;

    float acc[2][4][4] = {};

    {
#pragma unroll
        for (int i = 0; i < 4; i++) {
            int f = tid + i * 256;
            int row = f >> 3, c4 = (f & 7) * 4;
            CP_ASYNC16(a_u[0] + (unsigned)(row * 36 + c4) * 4,
                       g_o + (size_t)(m0 + row) * 512 + c4);
        }
#pragma unroll
        for (int i = 0; i < 2; i++) {
            int f = tid + i * 256;
            int row = f >> 4, c4 = (f & 15) * 4;
            CP_ASYNC16(w_u[0] + (unsigned)(row * 72 + c4) * 4,
                       g_wfcq + (size_t)row * 512 + n0 + c4);
        }
        CP_COMMIT;
    }
    int cur = 0;
    for (int k0 = 0; k0 < 512; k0 += 32) {
        CP_WAIT0;
        __syncthreads();
        if (k0 + 32 < 512) {
            unsigned au = a_u[cur ^ 1], wu = w_u[cur ^ 1];
#pragma unroll
            for (int i = 0; i < 4; i++) {
                int f = tid + i * 256;
                int row = f >> 3, c4 = (f & 7) * 4;
                CP_ASYNC16(au + (unsigned)(row * 36 + c4) * 4,
                           g_o + (size_t)(m0 + row) * 512 + k0 + 32 + c4);
            }
#pragma unroll
            for (int i = 0; i < 2; i++) {
                int f = tid + i * 256;
                int row = f >> 4, c4 = (f & 15) * 4;
                CP_ASYNC16(wu + (unsigned)(row * 72 + c4) * 4,
                           g_wfcq + (size_t)(k0 + 32 + row) * 512 + n0 + c4);
            }
            CP_COMMIT;
        }
        const unsigned* Asu = (const unsigned*)Ab[cur];
        const unsigned* Wsu = (const unsigned*)Wb[cur];
#pragma unroll
        for (int kk = 0; kk < 4; kk++) {
            int k = kk * 8;
            unsigned af[2][4], bf[4][2];
#pragma unroll
            for (int mb = 0; mb < 2; mb++) {
                int rb = warpM * 32 + mb * 16;
                af[mb][0] = Asu[(rb + g) * 36 + k + t];
                af[mb][1] = Asu[(rb + g + 8) * 36 + k + t];
                af[mb][2] = Asu[(rb + g) * 36 + k + t + 4];
                af[mb][3] = Asu[(rb + g + 8) * 36 + k + t + 4];
            }
#pragma unroll
            for (int nb = 0; nb < 4; nb++) {
                int cb = warpN * 32 + nb * 8 + g;
                bf[nb][0] = Wsu[(k + t) * 72 + cb];
                bf[nb][1] = Wsu[(k + t + 4) * 72 + cb];
            }
#pragma unroll
            for (int mb = 0; mb < 2; mb++)
#pragma unroll
                for (int nb = 0; nb < 4; nb++) MMA8(acc[mb][nb], af[mb], bf[nb])
        }
        cur ^= 1;
    }
    __syncthreads();
    // stage transposed (+ residual) in fsm, stride 132
#pragma unroll
    for (int mb = 0; mb < 2; mb++) {
        int el0 = warpM * 32 + mb * 16 + g;
#pragma unroll
        for (int nb = 0; nb < 4; nb++) {
            int nl = warpN * 32 + nb * 8 + 2 * t;
#pragma unroll
            for (int half = 0; half < 2; half++) {
                int el = el0 + half * 8;
                const float* res = g_s + (size_t)(m0 + el) * DM_ + n0 + nl;
                fsm[(nl + 0) * 132 + el] = acc[mb][nb][half * 2 + 0] + res[0];
                fsm[(nl + 1) * 132 + el] = acc[mb][nb][half * 2 + 1] + res[1];
            }
        }
    }
    __syncthreads();
#pragma unroll
    for (int i = 0; i < 8; i++) {
        int f = tid + i * 256;
        int row = f >> 5, c4 = (f & 31) * 4;
        float4 v = *(const float4*)&fsm[row * 132 + c4];
        *(float4*)(xout + ((size_t)b * DM_ + n0 + row) * E_ + e0 + c4) = v;
    }
}

// ---------------- 7. ape final -------------------------------------------------
__global__ void k_ape_final(float* __restrict__ ape) {
    int idx = blockIdx.x * 256 + threadIdx.x;
    int b = idx >> 10, j = idx & (E_ - 1);
    float cs = 0.f;
    const float* p = g_pcs2 + (size_t)b * 8 * 16 * E_ + j;
#pragma unroll 8
    for (int k = 0; k < 128; k++) cs += p[(size_t)k * E_];
    const unsigned char* dcol = g_d8 + (size_t)b * E_ * E_ + j;
    int cnt = 0;
#pragma unroll 8
    for (int i = 0; i < E_; i++) cnt += (dcol[(size_t)i * E_] <= MAXN_) ? 1 : 0;
    ape[idx] = cs / (float)cnt;
}

// ---------------- launch ------------------------------------------------------
extern "C" void kernel_launch(void* const* d_in, const int* in_sizes, int n_in,
                              void* d_out, int out_size) {
    const float* x        = (const float*)d_in[0];
    const int*   dist     = (const int*)  d_in[1];
    const float* base_rpr = (const float*)d_in[2];
    const float* w_q      = (const float*)d_in[3];
    const float* w_k      = (const float*)d_in[4];
    const float* w_v      = (const float*)d_in[5];
    const float* w_fc     = (const float*)d_in[6];
    const float* ln_g     = (const float*)d_in[7];
    const float* ln_b     = (const float*)d_in[8];

    float* x_out = (float*)d_out;
    float* attn  = x_out + (size_t)B_ * DM_ * E_;
    float* ape   = attn  + (size_t)B_ * H_ * E_ * E_;

    static int smem_set = 0;
    if (!smem_set) {
        cudaFuncSetAttribute(k_flash, cudaFuncAttributeMaxDynamicSharedMemorySize,
                             SM_TOTAL * 4);
        cudaFuncSetAttribute(k_qkv_mma, cudaFuncAttributeMaxDynamicSharedMemorySize,
                             QKV_SM * 4);
        cudaFuncSetAttribute(k_fc_mma, cudaFuncAttributeMaxDynamicSharedMemorySize,
                             FC_SM * 4);
        smem_set = 1;
    }

    k_transpose<<<dim3(E_ / 32, DM_ / 32, B_), dim3(32, 8)>>>(x);
    k_layernorm<<<B_ * E_, 256>>>(ln_g, ln_b);
    k_pack_prep<<<3072, 256>>>(dist, w_q, w_k, w_v, w_fc);

    k_qkv_mma<<<dim3(E_ / 128, 24, B_), 256, QKV_SM * 4>>>();

    k_flash<<<dim3(16, B_ * H_), 256, SM_TOTAL * 4>>>(base_rpr, attn);
    k_fc_mma<<<dim3(B_ * E_ / 128, DM_ / 64, 1), 256, FC_SM * 4>>>(x_out);
    k_ape_final<<<(B_ * E_) / 256, 256>>>(ape);
}